// round 2
// baseline (speedup 1.0000x reference)
#include <cuda_runtime.h>
#include <cstdint>

// Problem constants (fixed shapes per reference)
#define NMAX 100000
#define EMAX 1600000
#define HDIM 128
#define G3   384   // 3 * HG

// ---------------- scratch (device globals; allocation-free) ----------------
__device__ float g_xh[(size_t)NMAX * HDIM];
__device__ float g_xw[(size_t)NMAX * HDIM];
__device__ float g_agg[(size_t)NMAX * HDIM];
__device__ float g_h[(size_t)NMAX * HDIM];
__device__ float g_gi[(size_t)NMAX * G3];
__device__ float g_gh[(size_t)NMAX * G3];
__device__ float g_deg[NMAX];
__device__ float g_dinv[NMAX];
__device__ float g_norm[EMAX];
__device__ float g_WihT[HDIM * G3];
__device__ float g_WhhT[HDIM * G3];

// ---------------- small utility kernels ----------------

__global__ void transpose_g_kernel(const float* __restrict__ W, float* __restrict__ WT,
                                   int rows, int cols) {
    int idx = blockIdx.x * blockDim.x + threadIdx.x;
    if (idx < rows * cols) {
        int r = idx / cols, c = idx % cols;
        WT[c * rows + r] = W[idx];
    }
}

__global__ void init_deg_kernel(float* __restrict__ deg, int n) {
    int i = blockIdx.x * blockDim.x + threadIdx.x;
    if (i < n) deg[i] = 1.0f;
}

__global__ void deg_accum_kernel(const int* __restrict__ dst, const float* __restrict__ ew,
                                 float* __restrict__ deg, int E) {
    int e = blockIdx.x * blockDim.x + threadIdx.x;
    if (e < E) atomicAdd(&deg[dst[e]], ew[e]);
}

__global__ void dinv_kernel(const float* __restrict__ deg, float* __restrict__ dinv, int n) {
    int i = blockIdx.x * blockDim.x + threadIdx.x;
    if (i < n) {
        float d = deg[i];
        dinv[i] = (d > 0.0f) ? rsqrtf(d) : 0.0f;
    }
}

__global__ void norm_kernel(const int* __restrict__ src, const int* __restrict__ dst,
                            const float* __restrict__ ew, const float* __restrict__ dinv,
                            float* __restrict__ norm, int E) {
    int e = blockIdx.x * blockDim.x + threadIdx.x;
    if (e < E) norm[e] = dinv[src[e]] * ew[e] * dinv[dst[e]];
}

__global__ void zero_kernel(float* __restrict__ p, size_t n) {
    size_t i = (size_t)blockIdx.x * blockDim.x + threadIdx.x;
    size_t stride = (size_t)gridDim.x * blockDim.x;
    for (; i < n; i += stride) p[i] = 0.0f;
}

// ---------------- tf32 helpers ----------------
__device__ __forceinline__ void split_tf32(float x, uint32_t& hi, uint32_t& lo) {
    uint32_t h;
    asm("cvt.rna.tf32.f32 %0, %1;" : "=r"(h) : "f"(x));
    float l = x - __uint_as_float(h);
    uint32_t lw;
    asm("cvt.rna.tf32.f32 %0, %1;" : "=r"(lw) : "f"(l));
    hi = h; lo = lw;
}

__device__ __forceinline__ void mma_tf32(float (&d)[4], const uint32_t* a, const uint32_t* b) {
    asm volatile(
        "mma.sync.aligned.m16n8k8.row.col.f32.tf32.tf32.f32 "
        "{%0,%1,%2,%3}, {%4,%5,%6,%7}, {%8,%9}, {%0,%1,%2,%3};"
        : "+f"(d[0]), "+f"(d[1]), "+f"(d[2]), "+f"(d[3])
        : "r"(a[0]), "r"(a[1]), "r"(a[2]), "r"(a[3]), "r"(b[0]), "r"(b[1]));
}

// ---------------- 3xTF32 GEMM: C[M,Nc] = A[M,128] @ B[128,Nc] (+bias)(+relu) ----------------
// BM=128, BN=64, BK=16, 256 threads (8 warps, 2x4), warp tile 64x16 via m16n8k8.
#define TBM 128
#define TBN 64
#define TBK 16
#define ASTRIDE 136
#define BSTRIDE 72

template <int ACT>
__global__ __launch_bounds__(256) void gemm_tf32(
    const float* __restrict__ A, const float* __restrict__ B,
    const float* __restrict__ bias, float* __restrict__ C, int M, int Nc)
{
    __shared__ uint32_t sAh[TBK][ASTRIDE];
    __shared__ uint32_t sAl[TBK][ASTRIDE];
    __shared__ uint32_t sBh[TBK][BSTRIDE];
    __shared__ uint32_t sBl[TBK][BSTRIDE];

    const int tid = threadIdx.x;
    const int lane = tid & 31;
    const int wid = tid >> 5;
    const int wm = (wid >> 2) * 64;   // warp row base within tile (0 or 64)
    const int wn = (wid & 3) * 16;    // warp col base within tile
    const int m0 = blockIdx.y * TBM;
    const int n0 = blockIdx.x * TBN;

    const int gr = lane >> 2;  // group id
    const int gc = lane & 3;   // thread in group

    float acc[4][2][4];
#pragma unroll
    for (int i = 0; i < 4; i++)
#pragma unroll
        for (int j = 0; j < 2; j++)
#pragma unroll
            for (int k = 0; k < 4; k++) acc[i][j][k] = 0.0f;

    // A-load mapping: idx in [0,512): row = idx>>2, kq = idx&3 (float4 along k)
    // B-load mapping: idx in [0,256): k = idx>>4, n4 = (idx&15)*4

    for (int kc = 0; kc < 8; kc++) {
        const int k0 = kc * TBK;
        // ---- load A tile (128 x 16) with hi/lo split, swizzled store ----
#pragma unroll
        for (int i = 0; i < 2; i++) {
            int idx = tid + (i << 8);
            int row = idx >> 2;
            int kq = idx & 3;
            float4 v = make_float4(0.f, 0.f, 0.f, 0.f);
            if (m0 + row < M)
                v = *(const float4*)(A + (size_t)(m0 + row) * 128 + k0 + (kq << 2));
            float vv[4] = {v.x, v.y, v.z, v.w};
#pragma unroll
            for (int s = 0; s < 4; s++) {
                int j = (s + kq) & 3;             // stagger to avoid STS conflicts
                int kk = (kq << 2) + j;
                int ksw = kk ^ (row & 3);         // XOR swizzle
                uint32_t hi, lo;
                split_tf32(vv[j], hi, lo);
                sAh[ksw][row] = hi;
                sAl[ksw][row] = lo;
            }
        }
        // ---- load B tile (16 x 64) with hi/lo split ----
        {
            int k = tid >> 4;
            int n4 = (tid & 15) << 2;
            float4 v = make_float4(0.f, 0.f, 0.f, 0.f);
            if (n0 + n4 + 3 < Nc) {
                v = *(const float4*)(B + (size_t)(k0 + k) * Nc + n0 + n4);
            } else {
                float tmp[4] = {0.f, 0.f, 0.f, 0.f};
#pragma unroll
                for (int j = 0; j < 4; j++)
                    if (n0 + n4 + j < Nc) tmp[j] = B[(size_t)(k0 + k) * Nc + n0 + n4 + j];
                v = make_float4(tmp[0], tmp[1], tmp[2], tmp[3]);
            }
            float vv[4] = {v.x, v.y, v.z, v.w};
#pragma unroll
            for (int j = 0; j < 4; j++) {
                uint32_t hi, lo;
                split_tf32(vv[j], hi, lo);
                sBh[k][n4 + j] = hi;
                sBl[k][n4 + j] = lo;
            }
        }
        __syncthreads();

        // ---- compute: 2 k-steps of 8 ----
#pragma unroll
        for (int ks = 0; ks < 2; ks++) {
            // load B fragments
            uint32_t bh[2][2], bl[2][2];
#pragma unroll
            for (int nf = 0; nf < 2; nf++) {
                int n = wn + nf * 8 + gr;
                int kb = ks * 8 + gc;
                bh[nf][0] = sBh[kb][n];     bh[nf][1] = sBh[kb + 4][n];
                bl[nf][0] = sBl[kb][n];     bl[nf][1] = sBl[kb + 4][n];
            }
            // load A fragments + MMA
#pragma unroll
            for (int mf = 0; mf < 4; mf++) {
                int row = wm + mf * 16 + gr;
                int ka = ks * 8 + gc;
                int k0sw = ka ^ (row & 3);
                int k1sw = (ka + 4) ^ (row & 3);
                uint32_t ah[4], al[4];
                ah[0] = sAh[k0sw][row];     ah[1] = sAh[k0sw][row + 8];
                ah[2] = sAh[k1sw][row];     ah[3] = sAh[k1sw][row + 8];
                al[0] = sAl[k0sw][row];     al[1] = sAl[k0sw][row + 8];
                al[2] = sAl[k1sw][row];     al[3] = sAl[k1sw][row + 8];
#pragma unroll
                for (int nf = 0; nf < 2; nf++) {
                    mma_tf32(acc[mf][nf], al, bh[nf]);   // lo*hi
                    mma_tf32(acc[mf][nf], ah, bl[nf]);   // hi*lo
                    mma_tf32(acc[mf][nf], ah, bh[nf]);   // hi*hi
                }
            }
        }
        __syncthreads();
    }

    // ---- epilogue ----
#pragma unroll
    for (int mf = 0; mf < 4; mf++) {
        int r0 = m0 + wm + mf * 16 + gr;
#pragma unroll
        for (int nf = 0; nf < 2; nf++) {
            int col = n0 + wn + nf * 8 + (gc << 1);
            if (col < Nc) {
                float b0 = 0.f, b1 = 0.f;
                bool c1ok = (col + 1 < Nc);
                if (bias) { b0 = bias[col]; if (c1ok) b1 = bias[col + 1]; }
                float v0 = acc[mf][nf][0] + b0;
                float v1 = acc[mf][nf][1] + b1;
                float v2 = acc[mf][nf][2] + b0;
                float v3 = acc[mf][nf][3] + b1;
                if (ACT == 1) {
                    v0 = fmaxf(v0, 0.f); v1 = fmaxf(v1, 0.f);
                    v2 = fmaxf(v2, 0.f); v3 = fmaxf(v3, 0.f);
                }
                if (r0 < M) {
                    if (c1ok) *(float2*)(C + (size_t)r0 * Nc + col) = make_float2(v0, v1);
                    else C[(size_t)r0 * Nc + col] = v0;
                }
                if (r0 + 8 < M) {
                    if (c1ok) *(float2*)(C + (size_t)(r0 + 8) * Nc + col) = make_float2(v2, v3);
                    else C[(size_t)(r0 + 8) * Nc + col] = v2;
                }
            }
        }
    }
}

// ---------------- GRU elementwise ----------------
__global__ void gru_kernel(const float* __restrict__ gi, const float* __restrict__ gh,
                           const float* __restrict__ hprev, float* __restrict__ hout, int N) {
    int idx = blockIdx.x * blockDim.x + threadIdx.x;
    if (idx >= N * HDIM) return;
    int i = idx >> 7;
    int j = idx & 127;
    size_t base = (size_t)i * G3;
    float ir = gi[base + j],        hr = gh[base + j];
    float iz = gi[base + 128 + j],  hz = gh[base + 128 + j];
    float in_ = gi[base + 256 + j], hn = gh[base + 256 + j];
    float r = 1.0f / (1.0f + expf(-(ir + hr)));
    float z = 1.0f / (1.0f + expf(-(iz + hz)));
    float n = tanhf(in_ + r * hn);
    hout[idx] = (1.0f - z) * n + z * hprev[idx];
}

// ---------------- edge scatter: one warp per edge, float4 vector atomics ----------------
__global__ __launch_bounds__(256) void scatter_kernel(
    const int* __restrict__ src, const int* __restrict__ dst,
    const float* __restrict__ norm, const float* __restrict__ xw,
    float* __restrict__ agg, int E)
{
    int e = (int)(((size_t)blockIdx.x * blockDim.x + threadIdx.x) >> 5);
    if (e >= E) return;
    int lane = threadIdx.x & 31;
    int s = __ldg(src + e);
    int d = __ldg(dst + e);
    float nm = __ldg(norm + e);
    float4 v = *(const float4*)(xw + (size_t)s * HDIM + (lane << 2));
    v.x *= nm; v.y *= nm; v.z *= nm; v.w *= nm;
    atomicAdd((float4*)(agg + (size_t)d * HDIM + (lane << 2)), v);
}

// ---------------- finalize GCN layer: agg + self-loop + bias, relu ----------------
__global__ void finalize_kernel(const float* __restrict__ agg, const float* __restrict__ xw,
                                const float* __restrict__ dinv, const float* __restrict__ bias,
                                float* __restrict__ xh, int N) {
    int idx = blockIdx.x * blockDim.x + threadIdx.x;
    if (idx >= N * HDIM) return;
    int i = idx >> 7;
    int j = idx & 127;
    float di = dinv[i];
    float v = agg[idx] + xw[idx] * di * di + bias[j];
    xh[idx] = fmaxf(v, 0.0f);
}

// ---------------- host launch ----------------
extern "C" void kernel_launch(void* const* d_in, const int* in_sizes, int n_in,
                              void* d_out, int out_size) {
    const float* x     = (const float*)d_in[0];
    const int*   ei    = (const int*)d_in[1];
    const float* ew    = (const float*)d_in[2];
    const float* h0    = (const float*)d_in[3];
    const float* linW  = (const float*)d_in[4];
    const float* linB  = (const float*)d_in[5];
    const float* convW = (const float*)d_in[6];   // [3,128,128]
    const float* convB = (const float*)d_in[7];   // [3,128]
    const float* Wih   = (const float*)d_in[8];   // [384,128]
    const float* Whh   = (const float*)d_in[9];   // [384,128]
    const float* bih   = (const float*)d_in[10];
    const float* bhh   = (const float*)d_in[11];
    const float* fcW   = (const float*)d_in[12];  // [128,40]
    const float* fcB   = (const float*)d_in[13];
    float* out = (float*)d_out;

    const int N = in_sizes[0] / HDIM;
    const int E = in_sizes[2];
    const int C = in_sizes[13];
    const int* src = ei;
    const int* dst = ei + E;

    float *p_xh, *p_xw, *p_agg, *p_h, *p_gi, *p_gh, *p_deg, *p_dinv, *p_norm, *p_WihT, *p_WhhT;
    cudaGetSymbolAddress((void**)&p_xh, g_xh);
    cudaGetSymbolAddress((void**)&p_xw, g_xw);
    cudaGetSymbolAddress((void**)&p_agg, g_agg);
    cudaGetSymbolAddress((void**)&p_h, g_h);
    cudaGetSymbolAddress((void**)&p_gi, g_gi);
    cudaGetSymbolAddress((void**)&p_gh, g_gh);
    cudaGetSymbolAddress((void**)&p_deg, g_deg);
    cudaGetSymbolAddress((void**)&p_dinv, g_dinv);
    cudaGetSymbolAddress((void**)&p_norm, g_norm);
    cudaGetSymbolAddress((void**)&p_WihT, g_WihT);
    cudaGetSymbolAddress((void**)&p_WhhT, g_WhhT);

    const int T = 256;
    auto cdiv = [](int a, int b) { return (a + b - 1) / b; };

    // 1) transpose GRU weights
    transpose_g_kernel<<<cdiv(G3 * HDIM, T), T>>>(Wih, p_WihT, G3, HDIM);
    transpose_g_kernel<<<cdiv(G3 * HDIM, T), T>>>(Whh, p_WhhT, G3, HDIM);

    // 2) graph normalization (invariant across the 3 conv layers)
    init_deg_kernel<<<cdiv(N, T), T>>>(p_deg, N);
    deg_accum_kernel<<<cdiv(E, T), T>>>(dst, ew, p_deg, E);
    dinv_kernel<<<cdiv(N, T), T>>>(p_deg, p_dinv, N);
    norm_kernel<<<cdiv(E, T), T>>>(src, dst, ew, p_dinv, p_norm, E);

    const int gy = cdiv(N, TBM);

    // 3) xh = relu(x @ linW + linB)
    gemm_tf32<1><<<dim3(cdiv(HDIM, TBN), gy), 256>>>(x, linW, linB, p_xh, N, HDIM);

    // 4) first GRU: h = GRU(xh, h0)
    gemm_tf32<0><<<dim3(cdiv(G3, TBN), gy), 256>>>(p_xh, p_WihT, bih, p_gi, N, G3);
    gemm_tf32<0><<<dim3(cdiv(G3, TBN), gy), 256>>>(h0, p_WhhT, bhh, p_gh, N, G3);
    gru_kernel<<<cdiv(N * HDIM, T), T>>>(p_gi, p_gh, h0, p_h, N);

    // 5) 3 GCN layers + GRU
    for (int l = 0; l < 3; l++) {
        gemm_tf32<0><<<dim3(cdiv(HDIM, TBN), gy), 256>>>(p_xh, convW + (size_t)l * HDIM * HDIM, nullptr, p_xw, N, HDIM);
        zero_kernel<<<2048, 256>>>(p_agg, (size_t)N * HDIM);
        scatter_kernel<<<(int)(((size_t)E * 32 + 255) / 256), 256>>>(src, dst, p_norm, p_xw, p_agg, E);
        finalize_kernel<<<cdiv(N * HDIM, T), T>>>(p_agg, p_xw, p_dinv, convB + (size_t)l * HDIM, p_xh, N);

        gemm_tf32<0><<<dim3(cdiv(G3, TBN), gy), 256>>>(p_xh, p_WihT, bih, p_gi, N, G3);
        gemm_tf32<0><<<dim3(cdiv(G3, TBN), gy), 256>>>(p_h, p_WhhT, bhh, p_gh, N, G3);
        gru_kernel<<<cdiv(N * HDIM, T), T>>>(p_gi, p_gh, p_h, p_h, N);
    }

    // 6) out = h @ fcW + fcB
    gemm_tf32<0><<<dim3(cdiv(C, TBN), gy), 256>>>(p_h, fcW, fcB, out, N, C);
}

// round 4
// speedup vs baseline: 1.2579x; 1.2579x over previous
#include <cuda_runtime.h>
#include <cuda_bf16.h>
#include <cstdint>

#define NMAX 100000
#define EMAX 1600000
#define HDIM 128
#define G3   384

// ---------------- scratch (device globals) ----------------
__device__ float g_xw[(size_t)NMAX * HDIM];
__device__ float g_agg[(size_t)NMAX * HDIM];
__device__ float g_h[(size_t)NMAX * HDIM];
__device__ float g_gi[(size_t)NMAX * G3];
__device__ float g_gh[(size_t)NMAX * G3];
__device__ float g_deg[NMAX];
__device__ float g_dinv[NMAX];
__device__ float g_norm[EMAX];

__device__ __nv_bfloat16 g_xhi[(size_t)NMAX * HDIM];
__device__ __nv_bfloat16 g_xlo[(size_t)NMAX * HDIM];
__device__ __nv_bfloat16 g_ahi[(size_t)NMAX * HDIM];
__device__ __nv_bfloat16 g_alo[(size_t)NMAX * HDIM];
__device__ __nv_bfloat16 g_hhi[(size_t)NMAX * HDIM];
__device__ __nv_bfloat16 g_hlo[(size_t)NMAX * HDIM];

// weights pre-split to bf16 hi/lo, layout [Ntot, 128] K-major (= B^T)
__device__ __nv_bfloat16 g_wlin_hi[128 * 128],  g_wlin_lo[128 * 128];
__device__ __nv_bfloat16 g_wconv_hi[3 * 128 * 128], g_wconv_lo[3 * 128 * 128];
__device__ __nv_bfloat16 g_wih_hi[G3 * 128],    g_wih_lo[G3 * 128];
__device__ __nv_bfloat16 g_whh_hi[G3 * 128],    g_whh_lo[G3 * 128];
__device__ __nv_bfloat16 g_wfc_hi[64 * 128],    g_wfc_lo[64 * 128];

// ---------------- mma/ldmatrix helpers ----------------
__device__ __forceinline__ uint32_t smem_u32(const void* p) {
    return (uint32_t)__cvta_generic_to_shared(p);
}
__device__ __forceinline__ void ldsm_x4(uint32_t& r0, uint32_t& r1, uint32_t& r2,
                                        uint32_t& r3, uint32_t addr) {
    asm volatile("ldmatrix.sync.aligned.m8n8.x4.shared.b16 {%0,%1,%2,%3}, [%4];"
                 : "=r"(r0), "=r"(r1), "=r"(r2), "=r"(r3) : "r"(addr));
}
__device__ __forceinline__ void ldsm_x2(uint32_t& r0, uint32_t& r1, uint32_t addr) {
    asm volatile("ldmatrix.sync.aligned.m8n8.x2.shared.b16 {%0,%1}, [%2];"
                 : "=r"(r0), "=r"(r1) : "r"(addr));
}
__device__ __forceinline__ void mma_bf16(float (&d)[4], const uint32_t* a, const uint32_t* b) {
    asm volatile(
        "mma.sync.aligned.m16n8k16.row.col.f32.bf16.bf16.f32 "
        "{%0,%1,%2,%3}, {%4,%5,%6,%7}, {%8,%9}, {%0,%1,%2,%3};"
        : "+f"(d[0]), "+f"(d[1]), "+f"(d[2]), "+f"(d[3])
        : "r"(a[0]), "r"(a[1]), "r"(a[2]), "r"(a[3]), "r"(b[0]), "r"(b[1]));
}

// ---------------- small utility kernels ----------------
__global__ void init_deg_kernel(float* __restrict__ deg, int n) {
    int i = blockIdx.x * blockDim.x + threadIdx.x;
    if (i < n) deg[i] = 1.0f;
}
__global__ void deg_accum_kernel(const int* __restrict__ dst, const float* __restrict__ ew,
                                 float* __restrict__ deg, int E) {
    int e = blockIdx.x * blockDim.x + threadIdx.x;
    if (e < E) atomicAdd(&deg[dst[e]], ew[e]);
}
__global__ void dinv_kernel(const float* __restrict__ deg, float* __restrict__ dinv, int n) {
    int i = blockIdx.x * blockDim.x + threadIdx.x;
    if (i < n) {
        float d = deg[i];
        dinv[i] = (d > 0.0f) ? rsqrtf(d) : 0.0f;
    }
}
__global__ void norm_kernel(const int* __restrict__ src, const int* __restrict__ dst,
                            const float* __restrict__ ew, const float* __restrict__ dinv,
                            float* __restrict__ norm, int E) {
    int e = blockIdx.x * blockDim.x + threadIdx.x;
    if (e < E) norm[e] = dinv[src[e]] * ew[e] * dinv[dst[e]];
}
__global__ void zero_kernel(float* __restrict__ p, size_t n) {
    size_t i = (size_t)blockIdx.x * blockDim.x + threadIdx.x;
    size_t stride = (size_t)gridDim.x * blockDim.x;
    for (; i < n; i += stride) p[i] = 0.0f;
}

__global__ void wsplit_kernel(const float* __restrict__ src, __nv_bfloat16* __restrict__ hi,
                              __nv_bfloat16* __restrict__ lo, int Nsrc, int Ntot, int trans) {
    int idx = blockIdx.x * blockDim.x + threadIdx.x;
    if (idx >= Ntot * 128) return;
    int n = idx >> 7, k = idx & 127;
    float v = 0.0f;
    if (n < Nsrc) v = trans ? src[(size_t)k * Nsrc + n] : src[(size_t)n * 128 + k];
    __nv_bfloat16 h = __float2bfloat16(v);
    hi[idx] = h;
    lo[idx] = __float2bfloat16(v - __bfloat162float(h));
}

__global__ void asplit_kernel(const float* __restrict__ src, __nv_bfloat16* __restrict__ hi,
                              __nv_bfloat16* __restrict__ lo, int n) {
    int i = blockIdx.x * blockDim.x + threadIdx.x;
    if (i >= n) return;
    float v = src[i];
    __nv_bfloat16 h = __float2bfloat16(v);
    hi[i] = h;
    lo[i] = __float2bfloat16(v - __bfloat162float(h));
}

// ---------------- bf16-split GEMM via mma.sync.m16n8k16 ----------------
// C[M,Nc] = (Ahi+Alo)[M,128] @ (Bhi+Blo)^T, B rows = [Nc,128] K-major.
// BM=128, BN=64, full K=128 in smem. 256 threads, warp tile 64x16.
// smem planes (dynamic): Ahi@0 (32KB), Alo@32768, Bhi@65536 (16KB), Blo@81920.
#define SA_HI 0
#define SA_LO 32768
#define SB_HI 65536
#define SB_LO 81920
#define GEMM_SMEM 98304

__device__ __forceinline__ uint32_t swz(int row, int chunk) {
    return (uint32_t)(row * 256 + ((chunk ^ (row & 7)) << 4));
}

template <int RELU, int WF32, int WBF16>
__global__ __launch_bounds__(256, 2) void gemm_bf16(
    const __nv_bfloat16* __restrict__ Ahi, const __nv_bfloat16* __restrict__ Alo,
    const __nv_bfloat16* __restrict__ Bhi, const __nv_bfloat16* __restrict__ Blo,
    const float* __restrict__ bias,
    float* __restrict__ C, __nv_bfloat16* __restrict__ Chi, __nv_bfloat16* __restrict__ Clo,
    int M, int Nc)
{
    extern __shared__ char sm[];
    __shared__ float s_bias[64];
    const uint32_t smb = smem_u32(sm);
    const int tid = threadIdx.x;
    const int lane = tid & 31;
    const int wid = tid >> 5;
    const int m0 = blockIdx.y << 7;
    const int n0 = blockIdx.x << 6;

    // ---- load A tile: 128 rows x 16 chunks (16B each), hi+lo ----
    for (int i = tid; i < 2048; i += 256) {
        int r = i >> 4, c = i & 15;
        uint4 vh = make_uint4(0, 0, 0, 0), vl = make_uint4(0, 0, 0, 0);
        if (m0 + r < M) {
            vh = *(const uint4*)(Ahi + (size_t)(m0 + r) * 128 + c * 8);
            vl = *(const uint4*)(Alo + (size_t)(m0 + r) * 128 + c * 8);
        }
        uint32_t off = swz(r, c);
        *(uint4*)(sm + SA_HI + off) = vh;
        *(uint4*)(sm + SA_LO + off) = vl;
    }
    // ---- load B tile: 64 rows x 16 chunks, hi+lo ----
    for (int i = tid; i < 1024; i += 256) {
        int r = i >> 4, c = i & 15;
        uint4 vh = make_uint4(0, 0, 0, 0), vl = make_uint4(0, 0, 0, 0);
        int gn = n0 + r;
        if (gn < Nc) {
            vh = *(const uint4*)(Bhi + (size_t)gn * 128 + c * 8);
            vl = *(const uint4*)(Blo + (size_t)gn * 128 + c * 8);
        }
        uint32_t off = swz(r, c);
        *(uint4*)(sm + SB_HI + off) = vh;
        *(uint4*)(sm + SB_LO + off) = vl;
    }
    if (tid < 64) {
        int gn = n0 + tid;
        s_bias[tid] = (bias && gn < Nc) ? bias[gn] : 0.0f;
    }
    __syncthreads();

    const int wm = (wid >> 2) << 6;   // 0 or 64
    const int wn = (wid & 3) << 4;    // 0,16,32,48

    float acc[4][2][4];
#pragma unroll
    for (int i = 0; i < 4; i++)
#pragma unroll
        for (int j = 0; j < 2; j++)
#pragma unroll
            for (int k = 0; k < 4; k++) acc[i][j][k] = 0.0f;

#pragma unroll
    for (int kk = 0; kk < 8; kk++) {
        // B fragments (both nf, hi+lo)
        uint32_t bh[2][2], bl[2][2];
#pragma unroll
        for (int nf = 0; nf < 2; nf++) {
            int row = wn + nf * 8 + (lane & 7);
            int chunk = kk * 2 + ((lane >> 3) & 1);
            uint32_t off = swz(row, chunk);
            ldsm_x2(bh[nf][0], bh[nf][1], smb + SB_HI + off);
            ldsm_x2(bl[nf][0], bl[nf][1], smb + SB_LO + off);
        }
#pragma unroll
        for (int mf = 0; mf < 4; mf++) {
            int row = wm + mf * 16 + (lane & 15);
            int chunk = kk * 2 + (lane >> 4);
            uint32_t off = swz(row, chunk);
            uint32_t ah[4], al[4];
            ldsm_x4(ah[0], ah[1], ah[2], ah[3], smb + SA_HI + off);
            ldsm_x4(al[0], al[1], al[2], al[3], smb + SA_LO + off);
#pragma unroll
            for (int nf = 0; nf < 2; nf++) {
                mma_bf16(acc[mf][nf], ah, bl[nf]);   // hi*lo
                mma_bf16(acc[mf][nf], al, bh[nf]);   // lo*hi
                mma_bf16(acc[mf][nf], ah, bh[nf]);   // hi*hi
            }
        }
    }

    // ---- epilogue ----
    const int gr = lane >> 2, gc = lane & 3;
#pragma unroll
    for (int mf = 0; mf < 4; mf++) {
        int r0 = m0 + wm + mf * 16 + gr;
#pragma unroll
        for (int nf = 0; nf < 2; nf++) {
            int col = n0 + wn + nf * 8 + (gc << 1);
            if (col >= Nc && WF32) continue;
            float b0 = s_bias[wn + nf * 8 + (gc << 1)];
            float b1 = s_bias[wn + nf * 8 + (gc << 1) + 1];
            float v0 = acc[mf][nf][0] + b0;
            float v1 = acc[mf][nf][1] + b1;
            float v2 = acc[mf][nf][2] + b0;
            float v3 = acc[mf][nf][3] + b1;
            if (RELU) {
                v0 = fmaxf(v0, 0.f); v1 = fmaxf(v1, 0.f);
                v2 = fmaxf(v2, 0.f); v3 = fmaxf(v3, 0.f);
            }
            if (WF32) {
                bool c1ok = (col + 1 < Nc);
                if (r0 < M) {
                    if (c1ok) *(float2*)(C + (size_t)r0 * Nc + col) = make_float2(v0, v1);
                    else C[(size_t)r0 * Nc + col] = v0;
                }
                if (r0 + 8 < M) {
                    if (c1ok) *(float2*)(C + (size_t)(r0 + 8) * Nc + col) = make_float2(v2, v3);
                    else C[(size_t)(r0 + 8) * Nc + col] = v2;
                }
            }
            if (WBF16) {
                // activation outputs: row stride is always HDIM=128
                if (r0 < M) {
                    __nv_bfloat16 h0 = __float2bfloat16(v0);
                    __nv_bfloat16 h1 = __float2bfloat16(v1);
                    __nv_bfloat162 hh; hh.x = h0; hh.y = h1;
                    __nv_bfloat162 ll;
                    ll.x = __float2bfloat16(v0 - __bfloat162float(h0));
                    ll.y = __float2bfloat16(v1 - __bfloat162float(h1));
                    *(__nv_bfloat162*)(Chi + (size_t)r0 * 128 + col) = hh;
                    *(__nv_bfloat162*)(Clo + (size_t)r0 * 128 + col) = ll;
                }
                if (r0 + 8 < M) {
                    __nv_bfloat16 h2 = __float2bfloat16(v2);
                    __nv_bfloat16 h3 = __float2bfloat16(v3);
                    __nv_bfloat162 hh; hh.x = h2; hh.y = h3;
                    __nv_bfloat162 ll;
                    ll.x = __float2bfloat16(v2 - __bfloat162float(h2));
                    ll.y = __float2bfloat16(v3 - __bfloat162float(h3));
                    *(__nv_bfloat162*)(Chi + (size_t)(r0 + 8) * 128 + col) = hh;
                    *(__nv_bfloat162*)(Clo + (size_t)(r0 + 8) * 128 + col) = ll;
                }
            }
        }
    }
}

// ---------------- GRU elementwise (emits fp32 h + bf16 split) ----------------
__global__ void gru_kernel(const float* __restrict__ gi, const float* __restrict__ gh,
                           const float* __restrict__ hprev, float* __restrict__ hout,
                           __nv_bfloat16* __restrict__ hhi, __nv_bfloat16* __restrict__ hlo,
                           int N) {
    int idx = blockIdx.x * blockDim.x + threadIdx.x;
    if (idx >= N * HDIM) return;
    int i = idx >> 7;
    int j = idx & 127;
    size_t base = (size_t)i * G3;
    float ir = gi[base + j],        hr = gh[base + j];
    float iz = gi[base + 128 + j],  hz = gh[base + 128 + j];
    float in_ = gi[base + 256 + j], hn = gh[base + 256 + j];
    float r = 1.0f / (1.0f + expf(-(ir + hr)));
    float z = 1.0f / (1.0f + expf(-(iz + hz)));
    float n = tanhf(in_ + r * hn);
    float hv = (1.0f - z) * n + z * hprev[idx];
    hout[idx] = hv;
    __nv_bfloat16 hh = __float2bfloat16(hv);
    hhi[idx] = hh;
    hlo[idx] = __float2bfloat16(hv - __bfloat162float(hh));
}

// ---------------- edge scatter: one warp per edge, float4 vector atomics ----------------
__global__ __launch_bounds__(256) void scatter_kernel(
    const int* __restrict__ src, const int* __restrict__ dst,
    const float* __restrict__ norm, const float* __restrict__ xw,
    float* __restrict__ agg, int E)
{
    int e = (int)(((size_t)blockIdx.x * blockDim.x + threadIdx.x) >> 5);
    if (e >= E) return;
    int lane = threadIdx.x & 31;
    int s = __ldg(src + e);
    int d = __ldg(dst + e);
    float nm = __ldg(norm + e);
    float4 v = *(const float4*)(xw + (size_t)s * HDIM + (lane << 2));
    v.x *= nm; v.y *= nm; v.z *= nm; v.w *= nm;
    atomicAdd((float4*)(agg + (size_t)d * HDIM + (lane << 2)), v);
}

// ---------------- finalize GCN layer -> bf16 split activation ----------------
__global__ void finalize_kernel(const float* __restrict__ agg, const float* __restrict__ xw,
                                const float* __restrict__ dinv, const float* __restrict__ bias,
                                __nv_bfloat16* __restrict__ ahi, __nv_bfloat16* __restrict__ alo,
                                int N) {
    int idx = blockIdx.x * blockDim.x + threadIdx.x;
    if (idx >= N * HDIM) return;
    int i = idx >> 7;
    int j = idx & 127;
    float di = dinv[i];
    float v = agg[idx] + xw[idx] * di * di + bias[j];
    v = fmaxf(v, 0.0f);
    __nv_bfloat16 h = __float2bfloat16(v);
    ahi[idx] = h;
    alo[idx] = __float2bfloat16(v - __bfloat162float(h));
}

// ---------------- host launch ----------------
extern "C" void kernel_launch(void* const* d_in, const int* in_sizes, int n_in,
                              void* d_out, int out_size) {
    const float* x     = (const float*)d_in[0];
    const int*   ei    = (const int*)d_in[1];
    const float* ew    = (const float*)d_in[2];
    const float* h0    = (const float*)d_in[3];
    const float* linW  = (const float*)d_in[4];
    const float* linB  = (const float*)d_in[5];
    const float* convW = (const float*)d_in[6];
    const float* convB = (const float*)d_in[7];
    const float* Wih   = (const float*)d_in[8];
    const float* Whh   = (const float*)d_in[9];
    const float* bih   = (const float*)d_in[10];
    const float* bhh   = (const float*)d_in[11];
    const float* fcW   = (const float*)d_in[12];
    const float* fcB   = (const float*)d_in[13];
    float* out = (float*)d_out;

    const int N = in_sizes[0] / HDIM;
    const int E = in_sizes[2];
    const int C = in_sizes[13];  // 40
    const int* src = ei;
    const int* dst = ei + E;

    float *p_xw, *p_agg, *p_h, *p_gi, *p_gh, *p_deg, *p_dinv, *p_norm;
    cudaGetSymbolAddress((void**)&p_xw, g_xw);
    cudaGetSymbolAddress((void**)&p_agg, g_agg);
    cudaGetSymbolAddress((void**)&p_h, g_h);
    cudaGetSymbolAddress((void**)&p_gi, g_gi);
    cudaGetSymbolAddress((void**)&p_gh, g_gh);
    cudaGetSymbolAddress((void**)&p_deg, g_deg);
    cudaGetSymbolAddress((void**)&p_dinv, g_dinv);
    cudaGetSymbolAddress((void**)&p_norm, g_norm);

    __nv_bfloat16 *p_xhi, *p_xlo, *p_ahi, *p_alo, *p_hhi, *p_hlo;
    cudaGetSymbolAddress((void**)&p_xhi, g_xhi);
    cudaGetSymbolAddress((void**)&p_xlo, g_xlo);
    cudaGetSymbolAddress((void**)&p_ahi, g_ahi);
    cudaGetSymbolAddress((void**)&p_alo, g_alo);
    cudaGetSymbolAddress((void**)&p_hhi, g_hhi);
    cudaGetSymbolAddress((void**)&p_hlo, g_hlo);

    __nv_bfloat16 *w_lin_h, *w_lin_l, *w_conv_h, *w_conv_l, *w_ih_h, *w_ih_l,
                  *w_hh_h, *w_hh_l, *w_fc_h, *w_fc_l;
    cudaGetSymbolAddress((void**)&w_lin_h, g_wlin_hi);
    cudaGetSymbolAddress((void**)&w_lin_l, g_wlin_lo);
    cudaGetSymbolAddress((void**)&w_conv_h, g_wconv_hi);
    cudaGetSymbolAddress((void**)&w_conv_l, g_wconv_lo);
    cudaGetSymbolAddress((void**)&w_ih_h, g_wih_hi);
    cudaGetSymbolAddress((void**)&w_ih_l, g_wih_lo);
    cudaGetSymbolAddress((void**)&w_hh_h, g_whh_hi);
    cudaGetSymbolAddress((void**)&w_hh_l, g_whh_lo);
    cudaGetSymbolAddress((void**)&w_fc_h, g_wfc_hi);
    cudaGetSymbolAddress((void**)&w_fc_l, g_wfc_lo);

    const int T = 256;
    auto cdiv = [](int a, int b) { return (a + b - 1) / b; };

    static bool attr_done = false;
    if (!attr_done) {
        cudaFuncSetAttribute(gemm_bf16<1,0,1>, cudaFuncAttributeMaxDynamicSharedMemorySize, GEMM_SMEM);
        cudaFuncSetAttribute(gemm_bf16<0,1,0>, cudaFuncAttributeMaxDynamicSharedMemorySize, GEMM_SMEM);
        attr_done = true;
    }

    // ---- weight prep ----
    wsplit_kernel<<<cdiv(128 * 128, T), T>>>(linW, w_lin_h, w_lin_l, 128, 128, 1);
    for (int l = 0; l < 3; l++)
        wsplit_kernel<<<cdiv(128 * 128, T), T>>>(convW + (size_t)l * 16384,
            w_conv_h + (size_t)l * 16384, w_conv_l + (size_t)l * 16384, 128, 128, 1);
    wsplit_kernel<<<cdiv(G3 * 128, T), T>>>(Wih, w_ih_h, w_ih_l, G3, G3, 0);
    wsplit_kernel<<<cdiv(G3 * 128, T), T>>>(Whh, w_hh_h, w_hh_l, G3, G3, 0);
    wsplit_kernel<<<cdiv(64 * 128, T), T>>>(fcW, w_fc_h, w_fc_l, C, 64, 1);

    // ---- activation prep ----
    asplit_kernel<<<cdiv(N * HDIM, T), T>>>(x, p_xhi, p_xlo, N * HDIM);
    asplit_kernel<<<cdiv(N * HDIM, T), T>>>(h0, p_hhi, p_hlo, N * HDIM);

    // ---- graph normalization ----
    init_deg_kernel<<<cdiv(N, T), T>>>(p_deg, N);
    deg_accum_kernel<<<cdiv(E, T), T>>>(dst, ew, p_deg, E);
    dinv_kernel<<<cdiv(N, T), T>>>(p_deg, p_dinv, N);
    norm_kernel<<<cdiv(E, T), T>>>(src, dst, ew, p_dinv, p_norm, E);

    const int gy = cdiv(N, 128);  // 782

    // xh = relu(x @ linW + linB) -> bf16 split
    gemm_bf16<1,0,1><<<dim3(2, gy), 256, GEMM_SMEM>>>(p_xhi, p_xlo, w_lin_h, w_lin_l,
        linB, nullptr, p_ahi, p_alo, N, 128);

    // GRU 1
    gemm_bf16<0,1,0><<<dim3(6, gy), 256, GEMM_SMEM>>>(p_ahi, p_alo, w_ih_h, w_ih_l,
        bih, p_gi, nullptr, nullptr, N, G3);
    gemm_bf16<0,1,0><<<dim3(6, gy), 256, GEMM_SMEM>>>(p_hhi, p_hlo, w_hh_h, w_hh_l,
        bhh, p_gh, nullptr, nullptr, N, G3);
    gru_kernel<<<cdiv(N * HDIM, T), T>>>(p_gi, p_gh, h0, p_h, p_hhi, p_hlo, N);

    // 3 GCN layers + GRU
    for (int l = 0; l < 3; l++) {
        gemm_bf16<0,1,0><<<dim3(2, gy), 256, GEMM_SMEM>>>(p_ahi, p_alo,
            w_conv_h + (size_t)l * 16384, w_conv_l + (size_t)l * 16384,
            nullptr, p_xw, nullptr, nullptr, N, 128);
        zero_kernel<<<2048, 256>>>(p_agg, (size_t)N * HDIM);
        scatter_kernel<<<(int)(((size_t)E * 32 + 255) / 256), 256>>>(src, dst, p_norm, p_xw, p_agg, E);
        finalize_kernel<<<cdiv(N * HDIM, T), T>>>(p_agg, p_xw, p_dinv,
            convB + (size_t)l * HDIM, p_ahi, p_alo, N);

        gemm_bf16<0,1,0><<<dim3(6, gy), 256, GEMM_SMEM>>>(p_ahi, p_alo, w_ih_h, w_ih_l,
            bih, p_gi, nullptr, nullptr, N, G3);
        gemm_bf16<0,1,0><<<dim3(6, gy), 256, GEMM_SMEM>>>(p_hhi, p_hlo, w_hh_h, w_hh_l,
            bhh, p_gh, nullptr, nullptr, N, G3);
        gru_kernel<<<cdiv(N * HDIM, T), T>>>(p_gi, p_gh, p_h, p_h, p_hhi, p_hlo, N);
    }

    // out = h @ fcW + fcB
    gemm_bf16<0,1,0><<<dim3(1, gy), 256, GEMM_SMEM>>>(p_hhi, p_hlo, w_fc_h, w_fc_l,
        fcB, out, nullptr, nullptr, N, C);
}

// round 5
// speedup vs baseline: 1.4319x; 1.1383x over previous
#include <cuda_runtime.h>
#include <cuda_bf16.h>
#include <cuda_fp16.h>
#include <cstdint>

#define NMAX 100000
#define EMAX 1600000
#define HDIM 128
#define G3   384

// ---------------- scratch (device globals) ----------------
__device__ float g_xw[(size_t)NMAX * HDIM];
__device__ float g_agg[(size_t)NMAX * HDIM];
__device__ __half g_gi[(size_t)NMAX * G3];
__device__ float g_deg[NMAX];
__device__ float g_dinv[NMAX];
__device__ float g_norm[EMAX];

__device__ __nv_bfloat16 g_xhi[(size_t)NMAX * HDIM];
__device__ __nv_bfloat16 g_xlo[(size_t)NMAX * HDIM];
__device__ __nv_bfloat16 g_ahi[(size_t)NMAX * HDIM];
__device__ __nv_bfloat16 g_alo[(size_t)NMAX * HDIM];
// ping-pong h (bf16 hi/lo only)
__device__ __nv_bfloat16 g_hAhi[(size_t)NMAX * HDIM];
__device__ __nv_bfloat16 g_hAlo[(size_t)NMAX * HDIM];
__device__ __nv_bfloat16 g_hBhi[(size_t)NMAX * HDIM];
__device__ __nv_bfloat16 g_hBlo[(size_t)NMAX * HDIM];

// weights pre-split to bf16 hi/lo, layout [Ntot, 128] K-major (= B^T)
__device__ __nv_bfloat16 g_wlin_hi[128 * 128],  g_wlin_lo[128 * 128];
__device__ __nv_bfloat16 g_wconv_hi[3 * 128 * 128], g_wconv_lo[3 * 128 * 128];
__device__ __nv_bfloat16 g_wih_hi[G3 * 128],    g_wih_lo[G3 * 128];
__device__ __nv_bfloat16 g_whh_hi[G3 * 128],    g_whh_lo[G3 * 128];
__device__ __nv_bfloat16 g_wfc_hi[64 * 128],    g_wfc_lo[64 * 128];

// ---------------- mma/ldmatrix helpers ----------------
__device__ __forceinline__ uint32_t smem_u32(const void* p) {
    return (uint32_t)__cvta_generic_to_shared(p);
}
__device__ __forceinline__ void ldsm_x4(uint32_t& r0, uint32_t& r1, uint32_t& r2,
                                        uint32_t& r3, uint32_t addr) {
    asm volatile("ldmatrix.sync.aligned.m8n8.x4.shared.b16 {%0,%1,%2,%3}, [%4];"
                 : "=r"(r0), "=r"(r1), "=r"(r2), "=r"(r3) : "r"(addr));
}
__device__ __forceinline__ void ldsm_x2(uint32_t& r0, uint32_t& r1, uint32_t addr) {
    asm volatile("ldmatrix.sync.aligned.m8n8.x2.shared.b16 {%0,%1}, [%2];"
                 : "=r"(r0), "=r"(r1) : "r"(addr));
}
__device__ __forceinline__ void mma_bf16(float (&d)[4], const uint32_t* a, const uint32_t* b) {
    asm volatile(
        "mma.sync.aligned.m16n8k16.row.col.f32.bf16.bf16.f32 "
        "{%0,%1,%2,%3}, {%4,%5,%6,%7}, {%8,%9}, {%0,%1,%2,%3};"
        : "+f"(d[0]), "+f"(d[1]), "+f"(d[2]), "+f"(d[3])
        : "r"(a[0]), "r"(a[1]), "r"(a[2]), "r"(a[3]), "r"(b[0]), "r"(b[1]));
}
__device__ __forceinline__ uint32_t swz(int row, int chunk) {
    return (uint32_t)(row * 256 + ((chunk ^ (row & 7)) << 4));
}

// ---------------- small utility kernels ----------------
__global__ void init_deg_kernel(float* __restrict__ deg, int n) {
    int i = blockIdx.x * blockDim.x + threadIdx.x;
    if (i < n) deg[i] = 1.0f;
}
__global__ void deg_accum_kernel(const int* __restrict__ dst, const float* __restrict__ ew,
                                 float* __restrict__ deg, int E) {
    int e = blockIdx.x * blockDim.x + threadIdx.x;
    if (e < E) atomicAdd(&deg[dst[e]], ew[e]);
}
__global__ void dinv_kernel(const float* __restrict__ deg, float* __restrict__ dinv, int n) {
    int i = blockIdx.x * blockDim.x + threadIdx.x;
    if (i < n) {
        float d = deg[i];
        dinv[i] = (d > 0.0f) ? rsqrtf(d) : 0.0f;
    }
}
__global__ void norm_kernel(const int* __restrict__ src, const int* __restrict__ dst,
                            const float* __restrict__ ew, const float* __restrict__ dinv,
                            float* __restrict__ norm, int E) {
    int e = blockIdx.x * blockDim.x + threadIdx.x;
    if (e < E) norm[e] = dinv[src[e]] * ew[e] * dinv[dst[e]];
}
__global__ void zero_kernel(float* __restrict__ p, size_t n) {
    size_t i = (size_t)blockIdx.x * blockDim.x + threadIdx.x;
    size_t stride = (size_t)gridDim.x * blockDim.x;
    for (; i < n; i += stride) p[i] = 0.0f;
}
__global__ void wsplit_kernel(const float* __restrict__ src, __nv_bfloat16* __restrict__ hi,
                              __nv_bfloat16* __restrict__ lo, int Nsrc, int Ntot, int trans) {
    int idx = blockIdx.x * blockDim.x + threadIdx.x;
    if (idx >= Ntot * 128) return;
    int n = idx >> 7, k = idx & 127;
    float v = 0.0f;
    if (n < Nsrc) v = trans ? src[(size_t)k * Nsrc + n] : src[(size_t)n * 128 + k];
    __nv_bfloat16 h = __float2bfloat16(v);
    hi[idx] = h;
    lo[idx] = __float2bfloat16(v - __bfloat162float(h));
}
__global__ void asplit_kernel(const float* __restrict__ src, __nv_bfloat16* __restrict__ hi,
                              __nv_bfloat16* __restrict__ lo, int n) {
    int i = blockIdx.x * blockDim.x + threadIdx.x;
    if (i >= n) return;
    float v = src[i];
    __nv_bfloat16 h = __float2bfloat16(v);
    hi[i] = h;
    lo[i] = __float2bfloat16(v - __bfloat162float(h));
}

// ---------------- bf16-split GEMM via mma.sync.m16n8k16 ----------------
// OUT: 0 = fp32 C[M,Nc], 1 = fp16 C16[M,Nc], 2 = bf16 split Chi/Clo [M,128]
#define SA_HI 0
#define SA_LO 32768
#define SB_HI 65536
#define SB_LO 81920
#define GEMM_SMEM 98304

template <int RELU, int OUT>
__global__ __launch_bounds__(256, 2) void gemm_bf16(
    const __nv_bfloat16* __restrict__ Ahi, const __nv_bfloat16* __restrict__ Alo,
    const __nv_bfloat16* __restrict__ Bhi, const __nv_bfloat16* __restrict__ Blo,
    const float* __restrict__ bias,
    float* __restrict__ C, __half* __restrict__ C16,
    __nv_bfloat16* __restrict__ Chi, __nv_bfloat16* __restrict__ Clo,
    int M, int Nc)
{
    extern __shared__ char sm[];
    __shared__ float s_bias[64];
    const uint32_t smb = smem_u32(sm);
    const int tid = threadIdx.x;
    const int lane = tid & 31;
    const int wid = tid >> 5;
    const int m0 = blockIdx.y << 7;
    const int n0 = blockIdx.x << 6;

    for (int i = tid; i < 2048; i += 256) {
        int r = i >> 4, c = i & 15;
        uint4 vh = make_uint4(0, 0, 0, 0), vl = make_uint4(0, 0, 0, 0);
        if (m0 + r < M) {
            vh = *(const uint4*)(Ahi + (size_t)(m0 + r) * 128 + c * 8);
            vl = *(const uint4*)(Alo + (size_t)(m0 + r) * 128 + c * 8);
        }
        uint32_t off = swz(r, c);
        *(uint4*)(sm + SA_HI + off) = vh;
        *(uint4*)(sm + SA_LO + off) = vl;
    }
    for (int i = tid; i < 1024; i += 256) {
        int r = i >> 4, c = i & 15;
        uint4 vh = make_uint4(0, 0, 0, 0), vl = make_uint4(0, 0, 0, 0);
        int gn = n0 + r;
        if (gn < Nc) {
            vh = *(const uint4*)(Bhi + (size_t)gn * 128 + c * 8);
            vl = *(const uint4*)(Blo + (size_t)gn * 128 + c * 8);
        }
        uint32_t off = swz(r, c);
        *(uint4*)(sm + SB_HI + off) = vh;
        *(uint4*)(sm + SB_LO + off) = vl;
    }
    if (tid < 64) {
        int gn = n0 + tid;
        s_bias[tid] = (bias && gn < Nc) ? bias[gn] : 0.0f;
    }
    __syncthreads();

    const int wm = (wid >> 2) << 6;
    const int wn = (wid & 3) << 4;

    float acc[4][2][4];
#pragma unroll
    for (int i = 0; i < 4; i++)
#pragma unroll
        for (int j = 0; j < 2; j++)
#pragma unroll
            for (int k = 0; k < 4; k++) acc[i][j][k] = 0.0f;

#pragma unroll
    for (int kk = 0; kk < 8; kk++) {
        uint32_t bh[2][2], bl[2][2];
#pragma unroll
        for (int nf = 0; nf < 2; nf++) {
            int row = wn + nf * 8 + (lane & 7);
            int chunk = kk * 2 + ((lane >> 3) & 1);
            uint32_t off = swz(row, chunk);
            ldsm_x2(bh[nf][0], bh[nf][1], smb + SB_HI + off);
            ldsm_x2(bl[nf][0], bl[nf][1], smb + SB_LO + off);
        }
#pragma unroll
        for (int mf = 0; mf < 4; mf++) {
            int row = wm + mf * 16 + (lane & 15);
            int chunk = kk * 2 + (lane >> 4);
            uint32_t off = swz(row, chunk);
            uint32_t ah[4], al[4];
            ldsm_x4(ah[0], ah[1], ah[2], ah[3], smb + SA_HI + off);
            ldsm_x4(al[0], al[1], al[2], al[3], smb + SA_LO + off);
#pragma unroll
            for (int nf = 0; nf < 2; nf++) {
                mma_bf16(acc[mf][nf], ah, bl[nf]);
                mma_bf16(acc[mf][nf], al, bh[nf]);
                mma_bf16(acc[mf][nf], ah, bh[nf]);
            }
        }
    }

    const int gr = lane >> 2, gc = lane & 3;
#pragma unroll
    for (int mf = 0; mf < 4; mf++) {
        int r0 = m0 + wm + mf * 16 + gr;
#pragma unroll
        for (int nf = 0; nf < 2; nf++) {
            int cl = wn + nf * 8 + (gc << 1);
            int col = n0 + cl;
            float b0 = s_bias[cl], b1 = s_bias[cl + 1];
            float v0 = acc[mf][nf][0] + b0;
            float v1 = acc[mf][nf][1] + b1;
            float v2 = acc[mf][nf][2] + b0;
            float v3 = acc[mf][nf][3] + b1;
            if (RELU) {
                v0 = fmaxf(v0, 0.f); v1 = fmaxf(v1, 0.f);
                v2 = fmaxf(v2, 0.f); v3 = fmaxf(v3, 0.f);
            }
            if (OUT == 0) {
                if (col < Nc) {
                    bool c1ok = (col + 1 < Nc);
                    if (r0 < M) {
                        if (c1ok) *(float2*)(C + (size_t)r0 * Nc + col) = make_float2(v0, v1);
                        else C[(size_t)r0 * Nc + col] = v0;
                    }
                    if (r0 + 8 < M) {
                        if (c1ok) *(float2*)(C + (size_t)(r0 + 8) * Nc + col) = make_float2(v2, v3);
                        else C[(size_t)(r0 + 8) * Nc + col] = v2;
                    }
                }
            } else if (OUT == 1) {
                if (col + 1 < Nc) {
                    if (r0 < M)
                        *(__half2*)(C16 + (size_t)r0 * Nc + col) = __floats2half2_rn(v0, v1);
                    if (r0 + 8 < M)
                        *(__half2*)(C16 + (size_t)(r0 + 8) * Nc + col) = __floats2half2_rn(v2, v3);
                }
            } else {
                if (r0 < M) {
                    __nv_bfloat16 h0 = __float2bfloat16(v0);
                    __nv_bfloat16 h1 = __float2bfloat16(v1);
                    __nv_bfloat162 hh; hh.x = h0; hh.y = h1;
                    __nv_bfloat162 ll;
                    ll.x = __float2bfloat16(v0 - __bfloat162float(h0));
                    ll.y = __float2bfloat16(v1 - __bfloat162float(h1));
                    *(__nv_bfloat162*)(Chi + (size_t)r0 * 128 + col) = hh;
                    *(__nv_bfloat162*)(Clo + (size_t)r0 * 128 + col) = ll;
                }
                if (r0 + 8 < M) {
                    __nv_bfloat16 h2 = __float2bfloat16(v2);
                    __nv_bfloat16 h3 = __float2bfloat16(v3);
                    __nv_bfloat162 hh; hh.x = h2; hh.y = h3;
                    __nv_bfloat162 ll;
                    ll.x = __float2bfloat16(v2 - __bfloat162float(h2));
                    ll.y = __float2bfloat16(v3 - __bfloat162float(h3));
                    *(__nv_bfloat162*)(Chi + (size_t)(r0 + 8) * 128 + col) = hh;
                    *(__nv_bfloat162*)(Clo + (size_t)(r0 + 8) * 128 + col) = ll;
                }
            }
        }
    }
}

// ---------------- fused gh-GEMM + GRU ----------------
// gh = hprev @ Whh^T (+bhh), then GRU with gi (fp16) and hprev; writes h split (ping-pong).
// m-tile 64, grid (2, cdiv(M,64)). CTA computes cols [n0,n0+64) of each of 3 gates.
// smem 64KB: A_HI 0, A_LO 16K, W_HI 32K, W_LO 48K.
#define F_AH 0
#define F_AL 16384
#define F_WH 32768
#define F_WL 49152
#define FUSED_SMEM 65536

__global__ __launch_bounds__(256) void gru_fused(
    const __nv_bfloat16* __restrict__ Phi, const __nv_bfloat16* __restrict__ Plo,
    const __nv_bfloat16* __restrict__ Whi, const __nv_bfloat16* __restrict__ Wlo,
    const float* __restrict__ bhh,
    const __half* __restrict__ gi,
    __nv_bfloat16* __restrict__ Ohi, __nv_bfloat16* __restrict__ Olo,
    int M)
{
    extern __shared__ char sm[];
    __shared__ float s_bhh[192];
    const uint32_t smb = smem_u32(sm);
    const int tid = threadIdx.x;
    const int lane = tid & 31;
    const int wid = tid >> 5;
    const int m0 = blockIdx.y << 6;
    const int n0 = blockIdx.x << 6;

    // load hprev tile (64 rows x 128 K), hi/lo, swizzled
    for (int i = tid; i < 1024; i += 256) {
        int r = i >> 4, c = i & 15;
        uint4 vh = make_uint4(0, 0, 0, 0), vl = make_uint4(0, 0, 0, 0);
        if (m0 + r < M) {
            vh = *(const uint4*)(Phi + (size_t)(m0 + r) * 128 + c * 8);
            vl = *(const uint4*)(Plo + (size_t)(m0 + r) * 128 + c * 8);
        }
        uint32_t off = swz(r, c);
        *(uint4*)(sm + F_AH + off) = vh;
        *(uint4*)(sm + F_AL + off) = vl;
    }
    if (tid < 192) {
        int g = tid >> 6, c = tid & 63;
        s_bhh[tid] = bhh[g * 128 + n0 + c];
    }

    const int wm = (wid & 1) << 5;    // 0 or 32
    const int wn = (wid >> 1) << 4;   // 0,16,32,48

    float acc[3][2][2][4];
#pragma unroll
    for (int g = 0; g < 3; g++)
#pragma unroll
        for (int i = 0; i < 2; i++)
#pragma unroll
            for (int j = 0; j < 2; j++)
#pragma unroll
                for (int k = 0; k < 4; k++) acc[g][i][j][k] = 0.0f;

    for (int g = 0; g < 3; g++) {
        __syncthreads();
        // load Whh chunk: rows g*128+n0 .. +64
        for (int i = tid; i < 1024; i += 256) {
            int r = i >> 4, c = i & 15;
            int grow = g * 128 + n0 + r;
            uint4 vh = *(const uint4*)(Whi + (size_t)grow * 128 + c * 8);
            uint4 vl = *(const uint4*)(Wlo + (size_t)grow * 128 + c * 8);
            uint32_t off = swz(r, c);
            *(uint4*)(sm + F_WH + off) = vh;
            *(uint4*)(sm + F_WL + off) = vl;
        }
        __syncthreads();
#pragma unroll
        for (int kk = 0; kk < 8; kk++) {
            uint32_t bh[2][2], bl[2][2];
#pragma unroll
            for (int nf = 0; nf < 2; nf++) {
                int row = wn + nf * 8 + (lane & 7);
                int chunk = kk * 2 + ((lane >> 3) & 1);
                uint32_t off = swz(row, chunk);
                ldsm_x2(bh[nf][0], bh[nf][1], smb + F_WH + off);
                ldsm_x2(bl[nf][0], bl[nf][1], smb + F_WL + off);
            }
#pragma unroll
            for (int mf = 0; mf < 2; mf++) {
                int row = wm + mf * 16 + (lane & 15);
                int chunk = kk * 2 + (lane >> 4);
                uint32_t off = swz(row, chunk);
                uint32_t ah[4], al[4];
                ldsm_x4(ah[0], ah[1], ah[2], ah[3], smb + F_AH + off);
                ldsm_x4(al[0], al[1], al[2], al[3], smb + F_AL + off);
#pragma unroll
                for (int nf = 0; nf < 2; nf++) {
                    mma_bf16(acc[g][mf][nf], ah, bl[nf]);
                    mma_bf16(acc[g][mf][nf], al, bh[nf]);
                    mma_bf16(acc[g][mf][nf], ah, bh[nf]);
                }
            }
        }
    }

    // ---- GRU epilogue ----
    const int gr = lane >> 2, gc = lane & 3;
#pragma unroll
    for (int mf = 0; mf < 2; mf++) {
#pragma unroll
        for (int i2 = 0; i2 < 2; i2++) {
            int row = m0 + wm + mf * 16 + gr + i2 * 8;
            if (row >= M) continue;
#pragma unroll
            for (int nf = 0; nf < 2; nf++) {
                int cl = wn + nf * 8 + (gc << 1);
                int gcol = n0 + cl;
                // gi values (r,z,n gates), fp16 pairs
                const __half2 gi_r = *(const __half2*)(gi + (size_t)row * G3 + gcol);
                const __half2 gi_z = *(const __half2*)(gi + (size_t)row * G3 + 128 + gcol);
                const __half2 gi_n = *(const __half2*)(gi + (size_t)row * G3 + 256 + gcol);
                float ir0 = __low2float(gi_r),  ir1 = __high2float(gi_r);
                float iz0 = __low2float(gi_z),  iz1 = __high2float(gi_z);
                float in0 = __low2float(gi_n),  in1 = __high2float(gi_n);
                float hr0 = acc[0][mf][nf][i2 * 2 + 0] + s_bhh[cl];
                float hr1 = acc[0][mf][nf][i2 * 2 + 1] + s_bhh[cl + 1];
                float hz0 = acc[1][mf][nf][i2 * 2 + 0] + s_bhh[64 + cl];
                float hz1 = acc[1][mf][nf][i2 * 2 + 1] + s_bhh[64 + cl + 1];
                float hn0 = acc[2][mf][nf][i2 * 2 + 0] + s_bhh[128 + cl];
                float hn1 = acc[2][mf][nf][i2 * 2 + 1] + s_bhh[128 + cl + 1];
                // hprev reconstruct
                __nv_bfloat162 ph = *(const __nv_bfloat162*)(Phi + (size_t)row * 128 + gcol);
                __nv_bfloat162 pl = *(const __nv_bfloat162*)(Plo + (size_t)row * 128 + gcol);
                float hp0 = __bfloat162float(ph.x) + __bfloat162float(pl.x);
                float hp1 = __bfloat162float(ph.y) + __bfloat162float(pl.y);
                float r0 = 1.0f / (1.0f + expf(-(ir0 + hr0)));
                float r1 = 1.0f / (1.0f + expf(-(ir1 + hr1)));
                float z0 = 1.0f / (1.0f + expf(-(iz0 + hz0)));
                float z1 = 1.0f / (1.0f + expf(-(iz1 + hz1)));
                float n0v = tanhf(in0 + r0 * hn0);
                float n1v = tanhf(in1 + r1 * hn1);
                float h0 = (1.0f - z0) * n0v + z0 * hp0;
                float h1 = (1.0f - z1) * n1v + z1 * hp1;
                __nv_bfloat16 b0 = __float2bfloat16(h0);
                __nv_bfloat16 b1 = __float2bfloat16(h1);
                __nv_bfloat162 oh; oh.x = b0; oh.y = b1;
                __nv_bfloat162 ol;
                ol.x = __float2bfloat16(h0 - __bfloat162float(b0));
                ol.y = __float2bfloat16(h1 - __bfloat162float(b1));
                *(__nv_bfloat162*)(Ohi + (size_t)row * 128 + gcol) = oh;
                *(__nv_bfloat162*)(Olo + (size_t)row * 128 + gcol) = ol;
            }
        }
    }
}

// ---------------- edge scatter ----------------
__global__ __launch_bounds__(256) void scatter_kernel(
    const int* __restrict__ src, const int* __restrict__ dst,
    const float* __restrict__ norm, const float* __restrict__ xw,
    float* __restrict__ agg, int E)
{
    int e = (int)(((size_t)blockIdx.x * blockDim.x + threadIdx.x) >> 5);
    if (e >= E) return;
    int lane = threadIdx.x & 31;
    int s = __ldg(src + e);
    int d = __ldg(dst + e);
    float nm = __ldg(norm + e);
    float4 v = *(const float4*)(xw + (size_t)s * HDIM + (lane << 2));
    v.x *= nm; v.y *= nm; v.z *= nm; v.w *= nm;
    atomicAdd((float4*)(agg + (size_t)d * HDIM + (lane << 2)), v);
}

// ---------------- finalize GCN layer -> bf16 split ----------------
__global__ void finalize_kernel(const float* __restrict__ agg, const float* __restrict__ xw,
                                const float* __restrict__ dinv, const float* __restrict__ bias,
                                __nv_bfloat16* __restrict__ ahi, __nv_bfloat16* __restrict__ alo,
                                int N) {
    int idx = blockIdx.x * blockDim.x + threadIdx.x;
    if (idx >= N * HDIM) return;
    int i = idx >> 7;
    int j = idx & 127;
    float di = dinv[i];
    float v = agg[idx] + xw[idx] * di * di + bias[j];
    v = fmaxf(v, 0.0f);
    __nv_bfloat16 h = __float2bfloat16(v);
    ahi[idx] = h;
    alo[idx] = __float2bfloat16(v - __bfloat162float(h));
}

// ---------------- host launch ----------------
extern "C" void kernel_launch(void* const* d_in, const int* in_sizes, int n_in,
                              void* d_out, int out_size) {
    const float* x     = (const float*)d_in[0];
    const int*   ei    = (const int*)d_in[1];
    const float* ew    = (const float*)d_in[2];
    const float* h0    = (const float*)d_in[3];
    const float* linW  = (const float*)d_in[4];
    const float* linB  = (const float*)d_in[5];
    const float* convW = (const float*)d_in[6];
    const float* convB = (const float*)d_in[7];
    const float* Wih   = (const float*)d_in[8];
    const float* Whh   = (const float*)d_in[9];
    const float* bih   = (const float*)d_in[10];
    const float* bhh   = (const float*)d_in[11];
    const float* fcW   = (const float*)d_in[12];
    const float* fcB   = (const float*)d_in[13];
    float* out = (float*)d_out;

    const int N = in_sizes[0] / HDIM;
    const int E = in_sizes[2];
    const int C = in_sizes[13];  // 40
    const int* src = ei;
    const int* dst = ei + E;

    float *p_xw, *p_agg, *p_deg, *p_dinv, *p_norm;
    __half* p_gi;
    cudaGetSymbolAddress((void**)&p_xw, g_xw);
    cudaGetSymbolAddress((void**)&p_agg, g_agg);
    cudaGetSymbolAddress((void**)&p_gi, g_gi);
    cudaGetSymbolAddress((void**)&p_deg, g_deg);
    cudaGetSymbolAddress((void**)&p_dinv, g_dinv);
    cudaGetSymbolAddress((void**)&p_norm, g_norm);

    __nv_bfloat16 *p_xhi, *p_xlo, *p_ahi, *p_alo;
    __nv_bfloat16 *hA_hi, *hA_lo, *hB_hi, *hB_lo;
    cudaGetSymbolAddress((void**)&p_xhi, g_xhi);
    cudaGetSymbolAddress((void**)&p_xlo, g_xlo);
    cudaGetSymbolAddress((void**)&p_ahi, g_ahi);
    cudaGetSymbolAddress((void**)&p_alo, g_alo);
    cudaGetSymbolAddress((void**)&hA_hi, g_hAhi);
    cudaGetSymbolAddress((void**)&hA_lo, g_hAlo);
    cudaGetSymbolAddress((void**)&hB_hi, g_hBhi);
    cudaGetSymbolAddress((void**)&hB_lo, g_hBlo);

    __nv_bfloat16 *w_lin_h, *w_lin_l, *w_conv_h, *w_conv_l, *w_ih_h, *w_ih_l,
                  *w_hh_h, *w_hh_l, *w_fc_h, *w_fc_l;
    cudaGetSymbolAddress((void**)&w_lin_h, g_wlin_hi);
    cudaGetSymbolAddress((void**)&w_lin_l, g_wlin_lo);
    cudaGetSymbolAddress((void**)&w_conv_h, g_wconv_hi);
    cudaGetSymbolAddress((void**)&w_conv_l, g_wconv_lo);
    cudaGetSymbolAddress((void**)&w_ih_h, g_wih_hi);
    cudaGetSymbolAddress((void**)&w_ih_l, g_wih_lo);
    cudaGetSymbolAddress((void**)&w_hh_h, g_whh_hi);
    cudaGetSymbolAddress((void**)&w_hh_l, g_whh_lo);
    cudaGetSymbolAddress((void**)&w_fc_h, g_wfc_hi);
    cudaGetSymbolAddress((void**)&w_fc_l, g_wfc_lo);

    const int T = 256;
    auto cdiv = [](int a, int b) { return (a + b - 1) / b; };

    static bool attr_done = false;
    if (!attr_done) {
        cudaFuncSetAttribute(gemm_bf16<1,2>, cudaFuncAttributeMaxDynamicSharedMemorySize, GEMM_SMEM);
        cudaFuncSetAttribute(gemm_bf16<0,0>, cudaFuncAttributeMaxDynamicSharedMemorySize, GEMM_SMEM);
        cudaFuncSetAttribute(gemm_bf16<0,1>, cudaFuncAttributeMaxDynamicSharedMemorySize, GEMM_SMEM);
        cudaFuncSetAttribute(gru_fused, cudaFuncAttributeMaxDynamicSharedMemorySize, FUSED_SMEM);
        attr_done = true;
    }

    // ---- weight prep ----
    wsplit_kernel<<<cdiv(128 * 128, T), T>>>(linW, w_lin_h, w_lin_l, 128, 128, 1);
    for (int l = 0; l < 3; l++)
        wsplit_kernel<<<cdiv(128 * 128, T), T>>>(convW + (size_t)l * 16384,
            w_conv_h + (size_t)l * 16384, w_conv_l + (size_t)l * 16384, 128, 128, 1);
    wsplit_kernel<<<cdiv(G3 * 128, T), T>>>(Wih, w_ih_h, w_ih_l, G3, G3, 0);
    wsplit_kernel<<<cdiv(G3 * 128, T), T>>>(Whh, w_hh_h, w_hh_l, G3, G3, 0);
    wsplit_kernel<<<cdiv(64 * 128, T), T>>>(fcW, w_fc_h, w_fc_l, C, 64, 1);

    // ---- activation prep ----
    asplit_kernel<<<cdiv(N * HDIM, T), T>>>(x, p_xhi, p_xlo, N * HDIM);
    asplit_kernel<<<cdiv(N * HDIM, T), T>>>(h0, hA_hi, hA_lo, N * HDIM);

    // ---- graph normalization ----
    init_deg_kernel<<<cdiv(N, T), T>>>(p_deg, N);
    deg_accum_kernel<<<cdiv(E, T), T>>>(dst, ew, p_deg, E);
    dinv_kernel<<<cdiv(N, T), T>>>(p_deg, p_dinv, N);
    norm_kernel<<<cdiv(E, T), T>>>(src, dst, ew, p_dinv, p_norm, E);

    const int gy = cdiv(N, 128);   // 782
    const int gy64 = cdiv(N, 64);  // 1563

    // xh = relu(x @ linW + linB) -> bf16 split
    gemm_bf16<1,2><<<dim3(2, gy), 256, GEMM_SMEM>>>(p_xhi, p_xlo, w_lin_h, w_lin_l,
        linB, nullptr, nullptr, p_ahi, p_alo, N, 128);

    // GRU 1: gi = xh@Wih+bih (fp16); fused gh+GRU: hA -> hB
    gemm_bf16<0,1><<<dim3(6, gy), 256, GEMM_SMEM>>>(p_ahi, p_alo, w_ih_h, w_ih_l,
        bih, nullptr, p_gi, nullptr, nullptr, N, G3);
    gru_fused<<<dim3(2, gy64), 256, FUSED_SMEM>>>(hA_hi, hA_lo, w_hh_h, w_hh_l,
        bhh, p_gi, hB_hi, hB_lo, N);

    __nv_bfloat16 *cur_hi = hB_hi, *cur_lo = hB_lo;
    __nv_bfloat16 *nxt_hi = hA_hi, *nxt_lo = hA_lo;

    // 3 GCN layers + GRU
    for (int l = 0; l < 3; l++) {
        gemm_bf16<0,0><<<dim3(2, gy), 256, GEMM_SMEM>>>(p_ahi, p_alo,
            w_conv_h + (size_t)l * 16384, w_conv_l + (size_t)l * 16384,
            nullptr, p_xw, nullptr, nullptr, nullptr, N, 128);
        zero_kernel<<<2048, 256>>>(p_agg, (size_t)N * HDIM);
        scatter_kernel<<<(int)(((size_t)E * 32 + 255) / 256), 256>>>(src, dst, p_norm, p_xw, p_agg, E);
        finalize_kernel<<<cdiv(N * HDIM, T), T>>>(p_agg, p_xw, p_dinv,
            convB + (size_t)l * HDIM, p_ahi, p_alo, N);

        gemm_bf16<0,1><<<dim3(6, gy), 256, GEMM_SMEM>>>(p_ahi, p_alo, w_ih_h, w_ih_l,
            bih, nullptr, p_gi, nullptr, nullptr, N, G3);
        gru_fused<<<dim3(2, gy64), 256, FUSED_SMEM>>>(cur_hi, cur_lo, w_hh_h, w_hh_l,
            bhh, p_gi, nxt_hi, nxt_lo, N);
        __nv_bfloat16* t;
        t = cur_hi; cur_hi = nxt_hi; nxt_hi = t;
        t = cur_lo; cur_lo = nxt_lo; nxt_lo = t;
    }

    // out = h @ fcW + fcB
    gemm_bf16<0,0><<<dim3(1, gy), 256, GEMM_SMEM>>>(cur_hi, cur_lo, w_fc_h, w_fc_l,
        fcB, out, nullptr, nullptr, nullptr, N, C);
}

// round 6
// speedup vs baseline: 2.2238x; 1.5531x over previous
#include <cuda_runtime.h>
#include <cuda_bf16.h>
#include <cstdint>

#define NMAX 100000
#define EMAX 1600000
#define HDIM 128
#define G3   384

// ---------------- scratch (device globals) ----------------
__device__ float g_xw[(size_t)NMAX * HDIM];
__device__ float g_deg[NMAX];
__device__ float g_dinv[NMAX];
__device__ int   g_cnt[NMAX];
__device__ int   g_rowptr[NMAX + 1];
__device__ int   g_cursor[NMAX];
__device__ int   g_bsum[256];
__device__ int   g_eidx[EMAX];
__device__ float g_enorm[EMAX];

__device__ __nv_bfloat16 g_xhi[(size_t)NMAX * HDIM];
__device__ __nv_bfloat16 g_xlo[(size_t)NMAX * HDIM];
__device__ __nv_bfloat16 g_ahi[(size_t)NMAX * HDIM];
__device__ __nv_bfloat16 g_alo[(size_t)NMAX * HDIM];
__device__ __nv_bfloat16 g_hAhi[(size_t)NMAX * HDIM];
__device__ __nv_bfloat16 g_hAlo[(size_t)NMAX * HDIM];
__device__ __nv_bfloat16 g_hBhi[(size_t)NMAX * HDIM];
__device__ __nv_bfloat16 g_hBlo[(size_t)NMAX * HDIM];

__device__ __nv_bfloat16 g_wlin_hi[128 * 128],  g_wlin_lo[128 * 128];
__device__ __nv_bfloat16 g_wconv_hi[3 * 128 * 128], g_wconv_lo[3 * 128 * 128];
__device__ __nv_bfloat16 g_wih_hi[G3 * 128],    g_wih_lo[G3 * 128];
__device__ __nv_bfloat16 g_whh_hi[G3 * 128],    g_whh_lo[G3 * 128];
__device__ __nv_bfloat16 g_wfc_hi[64 * 128],    g_wfc_lo[64 * 128];

// ---------------- mma/ldmatrix helpers ----------------
__device__ __forceinline__ uint32_t smem_u32(const void* p) {
    return (uint32_t)__cvta_generic_to_shared(p);
}
__device__ __forceinline__ void ldsm_x4(uint32_t& r0, uint32_t& r1, uint32_t& r2,
                                        uint32_t& r3, uint32_t addr) {
    asm volatile("ldmatrix.sync.aligned.m8n8.x4.shared.b16 {%0,%1,%2,%3}, [%4];"
                 : "=r"(r0), "=r"(r1), "=r"(r2), "=r"(r3) : "r"(addr));
}
__device__ __forceinline__ void ldsm_x2(uint32_t& r0, uint32_t& r1, uint32_t addr) {
    asm volatile("ldmatrix.sync.aligned.m8n8.x2.shared.b16 {%0,%1}, [%2];"
                 : "=r"(r0), "=r"(r1) : "r"(addr));
}
__device__ __forceinline__ void mma_bf16(float* d, const uint32_t* a, const uint32_t* b) {
    asm volatile(
        "mma.sync.aligned.m16n8k16.row.col.f32.bf16.bf16.f32 "
        "{%0,%1,%2,%3}, {%4,%5,%6,%7}, {%8,%9}, {%0,%1,%2,%3};"
        : "+f"(d[0]), "+f"(d[1]), "+f"(d[2]), "+f"(d[3])
        : "r"(a[0]), "r"(a[1]), "r"(a[2]), "r"(a[3]), "r"(b[0]), "r"(b[1]));
}
__device__ __forceinline__ uint32_t swz(int row, int chunk) {
    return (uint32_t)(row * 256 + ((chunk ^ (row & 7)) << 4));
}

// ---------------- graph prep kernels ----------------
__global__ void init_deg_kernel(float* __restrict__ deg, int* __restrict__ cnt, int n) {
    int i = blockIdx.x * blockDim.x + threadIdx.x;
    if (i < n) { deg[i] = 1.0f; cnt[i] = 0; }
}
__global__ void deg_accum_kernel(const int* __restrict__ dst, const float* __restrict__ ew,
                                 float* __restrict__ deg, int* __restrict__ cnt, int E) {
    int e = blockIdx.x * blockDim.x + threadIdx.x;
    if (e < E) {
        int d = dst[e];
        atomicAdd(&deg[d], ew[e]);
        atomicAdd(&cnt[d], 1);
    }
}
__global__ void dinv_kernel(const float* __restrict__ deg, float* __restrict__ dinv, int n) {
    int i = blockIdx.x * blockDim.x + threadIdx.x;
    if (i < n) {
        float d = deg[i];
        dinv[i] = (d > 0.0f) ? rsqrtf(d) : 0.0f;
    }
}
// block-wise exclusive scan (block = 1024 elems)
__global__ void scan_block(const int* __restrict__ cnt, int* __restrict__ out,
                           int* __restrict__ bsum, int n) {
    __shared__ int sm[1024];
    int tx = threadIdx.x;
    int gid = blockIdx.x * 1024 + tx;
    int v = (gid < n) ? cnt[gid] : 0;
    sm[tx] = v;
    __syncthreads();
    for (int off = 1; off < 1024; off <<= 1) {
        int t = (tx >= off) ? sm[tx - off] : 0;
        __syncthreads();
        sm[tx] += t;
        __syncthreads();
    }
    if (gid < n) out[gid] = sm[tx] - v;  // exclusive
    if (tx == 1023) bsum[blockIdx.x] = sm[1023];
}
__global__ void scan_tops(int* __restrict__ bsum, int nb) {
    if (threadIdx.x == 0) {
        int acc = 0;
        for (int i = 0; i < nb; i++) { int v = bsum[i]; bsum[i] = acc; acc += v; }
    }
}
__global__ void scan_add(int* __restrict__ rowptr, int* __restrict__ cursor,
                         const int* __restrict__ bsum, int n, int E) {
    int gid = blockIdx.x * 1024 + threadIdx.x;
    if (gid < n) {
        int v = rowptr[gid] + bsum[blockIdx.x];
        rowptr[gid] = v;
        cursor[gid] = v;
    }
    if (gid == 0) rowptr[n] = E;
}
__global__ void fill_kernel(const int* __restrict__ src, const int* __restrict__ dst,
                            const float* __restrict__ ew, const float* __restrict__ dinv,
                            int* __restrict__ cursor, int* __restrict__ eidx,
                            float* __restrict__ enorm, int E) {
    int e = blockIdx.x * blockDim.x + threadIdx.x;
    if (e >= E) return;
    int s = src[e], d = dst[e];
    float nm = dinv[s] * ew[e] * dinv[d];
    int pos = atomicAdd(&cursor[d], 1);
    eidx[pos] = s;
    enorm[pos] = nm;
}

// ---------------- weight/activation split ----------------
__global__ void wsplit_kernel(const float* __restrict__ src, __nv_bfloat16* __restrict__ hi,
                              __nv_bfloat16* __restrict__ lo, int Nsrc, int Ntot, int trans) {
    int idx = blockIdx.x * blockDim.x + threadIdx.x;
    if (idx >= Ntot * 128) return;
    int n = idx >> 7, k = idx & 127;
    float v = 0.0f;
    if (n < Nsrc) v = trans ? src[(size_t)k * Nsrc + n] : src[(size_t)n * 128 + k];
    __nv_bfloat16 h = __float2bfloat16(v);
    hi[idx] = h;
    lo[idx] = __float2bfloat16(v - __bfloat162float(h));
}
__global__ void asplit_kernel(const float* __restrict__ src, __nv_bfloat16* __restrict__ hi,
                              __nv_bfloat16* __restrict__ lo, int n) {
    int i = blockIdx.x * blockDim.x + threadIdx.x;
    if (i >= n) return;
    float v = src[i];
    __nv_bfloat16 h = __float2bfloat16(v);
    hi[i] = h;
    lo[i] = __float2bfloat16(v - __bfloat162float(h));
}

// ---------------- bf16-split GEMM (OUT: 0=fp32 C, 2=bf16 split) ----------------
#define SA_HI 0
#define SA_LO 32768
#define SB_HI 65536
#define SB_LO 81920
#define GEMM_SMEM 98304

template <int RELU, int OUT>
__global__ __launch_bounds__(256, 2) void gemm_bf16(
    const __nv_bfloat16* __restrict__ Ahi, const __nv_bfloat16* __restrict__ Alo,
    const __nv_bfloat16* __restrict__ Bhi, const __nv_bfloat16* __restrict__ Blo,
    const float* __restrict__ bias,
    float* __restrict__ C,
    __nv_bfloat16* __restrict__ Chi, __nv_bfloat16* __restrict__ Clo,
    int M, int Nc)
{
    extern __shared__ char sm[];
    __shared__ float s_bias[64];
    const uint32_t smb = smem_u32(sm);
    const int tid = threadIdx.x;
    const int lane = tid & 31;
    const int wid = tid >> 5;
    const int m0 = blockIdx.y << 7;
    const int n0 = blockIdx.x << 6;

    for (int i = tid; i < 2048; i += 256) {
        int r = i >> 4, c = i & 15;
        uint4 vh = make_uint4(0, 0, 0, 0), vl = make_uint4(0, 0, 0, 0);
        if (m0 + r < M) {
            vh = *(const uint4*)(Ahi + (size_t)(m0 + r) * 128 + c * 8);
            vl = *(const uint4*)(Alo + (size_t)(m0 + r) * 128 + c * 8);
        }
        uint32_t off = swz(r, c);
        *(uint4*)(sm + SA_HI + off) = vh;
        *(uint4*)(sm + SA_LO + off) = vl;
    }
    for (int i = tid; i < 1024; i += 256) {
        int r = i >> 4, c = i & 15;
        uint4 vh = make_uint4(0, 0, 0, 0), vl = make_uint4(0, 0, 0, 0);
        int gn = n0 + r;
        if (gn < Nc) {
            vh = *(const uint4*)(Bhi + (size_t)gn * 128 + c * 8);
            vl = *(const uint4*)(Blo + (size_t)gn * 128 + c * 8);
        }
        uint32_t off = swz(r, c);
        *(uint4*)(sm + SB_HI + off) = vh;
        *(uint4*)(sm + SB_LO + off) = vl;
    }
    if (tid < 64) {
        int gn = n0 + tid;
        s_bias[tid] = (bias && gn < Nc) ? bias[gn] : 0.0f;
    }
    __syncthreads();

    const int wm = (wid >> 2) << 6;
    const int wn = (wid & 3) << 4;

    float acc[4][2][4];
#pragma unroll
    for (int i = 0; i < 4; i++)
#pragma unroll
        for (int j = 0; j < 2; j++)
#pragma unroll
            for (int k = 0; k < 4; k++) acc[i][j][k] = 0.0f;

#pragma unroll
    for (int kk = 0; kk < 8; kk++) {
        uint32_t bh[2][2], bl[2][2];
#pragma unroll
        for (int nf = 0; nf < 2; nf++) {
            int row = wn + nf * 8 + (lane & 7);
            int chunk = kk * 2 + ((lane >> 3) & 1);
            uint32_t off = swz(row, chunk);
            ldsm_x2(bh[nf][0], bh[nf][1], smb + SB_HI + off);
            ldsm_x2(bl[nf][0], bl[nf][1], smb + SB_LO + off);
        }
#pragma unroll
        for (int mf = 0; mf < 4; mf++) {
            int row = wm + mf * 16 + (lane & 15);
            int chunk = kk * 2 + (lane >> 4);
            uint32_t off = swz(row, chunk);
            uint32_t ah[4], al[4];
            ldsm_x4(ah[0], ah[1], ah[2], ah[3], smb + SA_HI + off);
            ldsm_x4(al[0], al[1], al[2], al[3], smb + SA_LO + off);
#pragma unroll
            for (int nf = 0; nf < 2; nf++) {
                mma_bf16(acc[mf][nf], ah, bl[nf]);
                mma_bf16(acc[mf][nf], al, bh[nf]);
                mma_bf16(acc[mf][nf], ah, bh[nf]);
            }
        }
    }

    const int gr = lane >> 2, gc = lane & 3;
#pragma unroll
    for (int mf = 0; mf < 4; mf++) {
        int r0 = m0 + wm + mf * 16 + gr;
#pragma unroll
        for (int nf = 0; nf < 2; nf++) {
            int cl = wn + nf * 8 + (gc << 1);
            int col = n0 + cl;
            float b0 = s_bias[cl], b1 = s_bias[cl + 1];
            float v0 = acc[mf][nf][0] + b0;
            float v1 = acc[mf][nf][1] + b1;
            float v2 = acc[mf][nf][2] + b0;
            float v3 = acc[mf][nf][3] + b1;
            if (RELU) {
                v0 = fmaxf(v0, 0.f); v1 = fmaxf(v1, 0.f);
                v2 = fmaxf(v2, 0.f); v3 = fmaxf(v3, 0.f);
            }
            if (OUT == 0) {
                if (col < Nc) {
                    bool c1ok = (col + 1 < Nc);
                    if (r0 < M) {
                        if (c1ok) *(float2*)(C + (size_t)r0 * Nc + col) = make_float2(v0, v1);
                        else C[(size_t)r0 * Nc + col] = v0;
                    }
                    if (r0 + 8 < M) {
                        if (c1ok) *(float2*)(C + (size_t)(r0 + 8) * Nc + col) = make_float2(v2, v3);
                        else C[(size_t)(r0 + 8) * Nc + col] = v2;
                    }
                }
            } else {
                if (r0 < M) {
                    __nv_bfloat16 h0 = __float2bfloat16(v0);
                    __nv_bfloat16 h1 = __float2bfloat16(v1);
                    __nv_bfloat162 hh; hh.x = h0; hh.y = h1;
                    __nv_bfloat162 ll;
                    ll.x = __float2bfloat16(v0 - __bfloat162float(h0));
                    ll.y = __float2bfloat16(v1 - __bfloat162float(h1));
                    *(__nv_bfloat162*)(Chi + (size_t)r0 * 128 + col) = hh;
                    *(__nv_bfloat162*)(Clo + (size_t)r0 * 128 + col) = ll;
                }
                if (r0 + 8 < M) {
                    __nv_bfloat16 h2 = __float2bfloat16(v2);
                    __nv_bfloat16 h3 = __float2bfloat16(v3);
                    __nv_bfloat162 hh; hh.x = h2; hh.y = h3;
                    __nv_bfloat162 ll;
                    ll.x = __float2bfloat16(v2 - __bfloat162float(h2));
                    ll.y = __float2bfloat16(v3 - __bfloat162float(h3));
                    *(__nv_bfloat162*)(Chi + (size_t)(r0 + 8) * 128 + col) = hh;
                    *(__nv_bfloat162*)(Clo + (size_t)(r0 + 8) * 128 + col) = ll;
                }
            }
        }
    }
}

// ---------------- fully-fused GRU: gi + gh GEMMs + elementwise ----------------
// m-tile 64, grid (2, cdiv(M,64)). Gates r,z: gi and gh accumulate into the SAME regs.
// smem: X_HI 0, X_LO 16K, P_HI 32K, P_LO 48K, W_HI 64K, W_LO 80K = 96KB.
#define MX_H 0
#define MX_L 16384
#define MP_H 32768
#define MP_L 49152
#define MW_H 65536
#define MW_L 81920
#define MEGA_SMEM 98304

__global__ __launch_bounds__(256, 2) void gru_mega(
    const __nv_bfloat16* __restrict__ Xhi, const __nv_bfloat16* __restrict__ Xlo,
    const __nv_bfloat16* __restrict__ Phi, const __nv_bfloat16* __restrict__ Plo,
    const __nv_bfloat16* __restrict__ Wih_h, const __nv_bfloat16* __restrict__ Wih_l,
    const __nv_bfloat16* __restrict__ Whh_h, const __nv_bfloat16* __restrict__ Whh_l,
    const float* __restrict__ bih, const float* __restrict__ bhh,
    __nv_bfloat16* __restrict__ Ohi, __nv_bfloat16* __restrict__ Olo,
    int M)
{
    extern __shared__ char sm[];
    __shared__ float s_brz[128], s_bin[64], s_bhn[64];
    const uint32_t smb = smem_u32(sm);
    const int tid = threadIdx.x;
    const int lane = tid & 31;
    const int wid = tid >> 5;
    const int m0 = blockIdx.y << 6;
    const int n0 = blockIdx.x << 6;

    // load X and P tiles (64 rows x 128), swizzled
    for (int i = tid; i < 1024; i += 256) {
        int r = i >> 4, c = i & 15;
        uint4 xh = make_uint4(0,0,0,0), xl = xh, ph = xh, pl = xh;
        if (m0 + r < M) {
            xh = *(const uint4*)(Xhi + (size_t)(m0 + r) * 128 + c * 8);
            xl = *(const uint4*)(Xlo + (size_t)(m0 + r) * 128 + c * 8);
            ph = *(const uint4*)(Phi + (size_t)(m0 + r) * 128 + c * 8);
            pl = *(const uint4*)(Plo + (size_t)(m0 + r) * 128 + c * 8);
        }
        uint32_t off = swz(r, c);
        *(uint4*)(sm + MX_H + off) = xh;
        *(uint4*)(sm + MX_L + off) = xl;
        *(uint4*)(sm + MP_H + off) = ph;
        *(uint4*)(sm + MP_L + off) = pl;
    }
    if (tid < 128) {
        int g = tid >> 6, c = tid & 63;
        s_brz[tid] = bih[g * 128 + n0 + c] + bhh[g * 128 + n0 + c];
    } else if (tid < 192) {
        int c = tid - 128;
        s_bin[c] = bih[256 + n0 + c];
        s_bhn[c] = bhh[256 + n0 + c];
    }

    const int wm = (wid & 1) << 5;    // 0 or 32
    const int wn = (wid >> 1) << 4;   // 0,16,32,48

    float accR[2][2][4], accZ[2][2][4], accI[2][2][4], accH[2][2][4];
#pragma unroll
    for (int i = 0; i < 2; i++)
#pragma unroll
        for (int j = 0; j < 2; j++)
#pragma unroll
            for (int k = 0; k < 4; k++) {
                accR[i][j][k] = 0.0f; accZ[i][j][k] = 0.0f;
                accI[i][j][k] = 0.0f; accH[i][j][k] = 0.0f;
            }

    // 6 stages: (g, which) for g=0..2, which=0 (Wih*X) / 1 (Whh*P)
#pragma unroll
    for (int st = 0; st < 6; st++) {
        const int g = st >> 1;
        const int wh = st & 1;
        const __nv_bfloat16* Wh = wh ? Whh_h : Wih_h;
        const __nv_bfloat16* Wl = wh ? Whh_l : Wih_l;
        const uint32_t aHi = wh ? MP_H : MX_H;
        const uint32_t aLo = wh ? MP_L : MX_L;
        float (*acc)[2][4] = (g == 0) ? accR : (g == 1) ? accZ : (wh ? accH : accI);

        __syncthreads();
        for (int i = tid; i < 1024; i += 256) {
            int r = i >> 4, c = i & 15;
            int grow = g * 128 + n0 + r;
            uint4 vh = *(const uint4*)(Wh + (size_t)grow * 128 + c * 8);
            uint4 vl = *(const uint4*)(Wl + (size_t)grow * 128 + c * 8);
            uint32_t off = swz(r, c);
            *(uint4*)(sm + MW_H + off) = vh;
            *(uint4*)(sm + MW_L + off) = vl;
        }
        __syncthreads();
#pragma unroll
        for (int kk = 0; kk < 8; kk++) {
            uint32_t bh[2][2], bl[2][2];
#pragma unroll
            for (int nf = 0; nf < 2; nf++) {
                int row = wn + nf * 8 + (lane & 7);
                int chunk = kk * 2 + ((lane >> 3) & 1);
                uint32_t off = swz(row, chunk);
                ldsm_x2(bh[nf][0], bh[nf][1], smb + MW_H + off);
                ldsm_x2(bl[nf][0], bl[nf][1], smb + MW_L + off);
            }
#pragma unroll
            for (int mf = 0; mf < 2; mf++) {
                int row = wm + mf * 16 + (lane & 15);
                int chunk = kk * 2 + (lane >> 4);
                uint32_t off = swz(row, chunk);
                uint32_t ah[4], al[4];
                ldsm_x4(ah[0], ah[1], ah[2], ah[3], smb + aHi + off);
                ldsm_x4(al[0], al[1], al[2], al[3], smb + aLo + off);
#pragma unroll
                for (int nf = 0; nf < 2; nf++) {
                    mma_bf16(acc[mf][nf], ah, bl[nf]);
                    mma_bf16(acc[mf][nf], al, bh[nf]);
                    mma_bf16(acc[mf][nf], ah, bh[nf]);
                }
            }
        }
    }

    // ---- GRU epilogue (hprev reconstructed from smem) ----
    const int gr = lane >> 2, gc = lane & 3;
#pragma unroll
    for (int mf = 0; mf < 2; mf++) {
#pragma unroll
        for (int i2 = 0; i2 < 2; i2++) {
            int lrow = wm + mf * 16 + gr + i2 * 8;
            int row = m0 + lrow;
            if (row >= M) continue;
#pragma unroll
            for (int nf = 0; nf < 2; nf++) {
                int cl = wn + nf * 8 + (gc << 1);
                int gcol = n0 + cl;
                float rr0 = accR[mf][nf][i2 * 2 + 0] + s_brz[cl];
                float rr1 = accR[mf][nf][i2 * 2 + 1] + s_brz[cl + 1];
                float zz0 = accZ[mf][nf][i2 * 2 + 0] + s_brz[64 + cl];
                float zz1 = accZ[mf][nf][i2 * 2 + 1] + s_brz[64 + cl + 1];
                float in0 = accI[mf][nf][i2 * 2 + 0] + s_bin[cl];
                float in1 = accI[mf][nf][i2 * 2 + 1] + s_bin[cl + 1];
                float hn0 = accH[mf][nf][i2 * 2 + 0] + s_bhn[cl];
                float hn1 = accH[mf][nf][i2 * 2 + 1] + s_bhn[cl + 1];
                // hprev from smem (swizzled): chunk = gcol>>3, byte within = (gcol&7)*2
                uint32_t poff = swz(lrow, gcol >> 3) + (gcol & 7) * 2;
                __nv_bfloat162 ph = *(__nv_bfloat162*)(sm + MP_H + poff);
                __nv_bfloat162 pl = *(__nv_bfloat162*)(sm + MP_L + poff);
                float hp0 = __bfloat162float(ph.x) + __bfloat162float(pl.x);
                float hp1 = __bfloat162float(ph.y) + __bfloat162float(pl.y);
                float r0 = 1.0f / (1.0f + expf(-rr0));
                float r1 = 1.0f / (1.0f + expf(-rr1));
                float z0 = 1.0f / (1.0f + expf(-zz0));
                float z1 = 1.0f / (1.0f + expf(-zz1));
                float n0v = tanhf(in0 + r0 * hn0);
                float n1v = tanhf(in1 + r1 * hn1);
                float h0 = (1.0f - z0) * n0v + z0 * hp0;
                float h1 = (1.0f - z1) * n1v + z1 * hp1;
                __nv_bfloat16 b0 = __float2bfloat16(h0);
                __nv_bfloat16 b1 = __float2bfloat16(h1);
                __nv_bfloat162 oh; oh.x = b0; oh.y = b1;
                __nv_bfloat162 ol;
                ol.x = __float2bfloat16(h0 - __bfloat162float(b0));
                ol.y = __float2bfloat16(h1 - __bfloat162float(b1));
                *(__nv_bfloat162*)(Ohi + (size_t)row * 128 + gcol) = oh;
                *(__nv_bfloat162*)(Olo + (size_t)row * 128 + gcol) = ol;
            }
        }
    }
}

// ---------------- CSR gather aggregation (replaces zero+scatter+finalize) ----------------
// one warp per node; lane covers 4 cols (float4). Adds self-loop + bias, relu, bf16 split.
__global__ __launch_bounds__(256) void aggregate_kernel(
    const int* __restrict__ rowptr, const int* __restrict__ eidx,
    const float* __restrict__ enorm, const float* __restrict__ xw,
    const float* __restrict__ dinv, const float* __restrict__ bias,
    __nv_bfloat16* __restrict__ ahi, __nv_bfloat16* __restrict__ alo, int N)
{
    int node = (int)(((size_t)blockIdx.x * blockDim.x + threadIdx.x) >> 5);
    if (node >= N) return;
    int lane = threadIdx.x & 31;
    int start = __ldg(rowptr + node);
    int end = __ldg(rowptr + node + 1);
    float a0 = 0.f, a1 = 0.f, a2 = 0.f, a3 = 0.f;
    for (int j = start; j < end; j++) {
        int s = __ldg(eidx + j);
        float nm = __ldg(enorm + j);
        float4 v = *(const float4*)(xw + (size_t)s * HDIM + (lane << 2));
        a0 += v.x * nm; a1 += v.y * nm; a2 += v.z * nm; a3 += v.w * nm;
    }
    float di = __ldg(dinv + node);
    float sw = di * di;
    float4 self = *(const float4*)(xw + (size_t)node * HDIM + (lane << 2));
    float4 bs = *(const float4*)(bias + (lane << 2));
    a0 = fmaxf(a0 + self.x * sw + bs.x, 0.f);
    a1 = fmaxf(a1 + self.y * sw + bs.y, 0.f);
    a2 = fmaxf(a2 + self.z * sw + bs.z, 0.f);
    a3 = fmaxf(a3 + self.w * sw + bs.w, 0.f);
    __nv_bfloat16 h0 = __float2bfloat16(a0), h1 = __float2bfloat16(a1);
    __nv_bfloat16 h2 = __float2bfloat16(a2), h3 = __float2bfloat16(a3);
    __nv_bfloat162 hh01; hh01.x = h0; hh01.y = h1;
    __nv_bfloat162 hh23; hh23.x = h2; hh23.y = h3;
    __nv_bfloat162 ll01, ll23;
    ll01.x = __float2bfloat16(a0 - __bfloat162float(h0));
    ll01.y = __float2bfloat16(a1 - __bfloat162float(h1));
    ll23.x = __float2bfloat16(a2 - __bfloat162float(h2));
    ll23.y = __float2bfloat16(a3 - __bfloat162float(h3));
    *(__nv_bfloat162*)(ahi + (size_t)node * HDIM + (lane << 2)) = hh01;
    *(__nv_bfloat162*)(ahi + (size_t)node * HDIM + (lane << 2) + 2) = hh23;
    *(__nv_bfloat162*)(alo + (size_t)node * HDIM + (lane << 2)) = ll01;
    *(__nv_bfloat162*)(alo + (size_t)node * HDIM + (lane << 2) + 2) = ll23;
}

// ---------------- host launch ----------------
extern "C" void kernel_launch(void* const* d_in, const int* in_sizes, int n_in,
                              void* d_out, int out_size) {
    const float* x     = (const float*)d_in[0];
    const int*   ei    = (const int*)d_in[1];
    const float* ew    = (const float*)d_in[2];
    const float* h0    = (const float*)d_in[3];
    const float* linW  = (const float*)d_in[4];
    const float* linB  = (const float*)d_in[5];
    const float* convW = (const float*)d_in[6];
    const float* convB = (const float*)d_in[7];
    const float* Wih   = (const float*)d_in[8];
    const float* Whh   = (const float*)d_in[9];
    const float* bih   = (const float*)d_in[10];
    const float* bhh   = (const float*)d_in[11];
    const float* fcW   = (const float*)d_in[12];
    const float* fcB   = (const float*)d_in[13];
    float* out = (float*)d_out;

    const int N = in_sizes[0] / HDIM;
    const int E = in_sizes[2];
    const int C = in_sizes[13];  // 40
    const int* src = ei;
    const int* dst = ei + E;

    float *p_xw, *p_deg, *p_dinv, *p_enorm;
    int *p_cnt, *p_rowptr, *p_cursor, *p_bsum, *p_eidx;
    cudaGetSymbolAddress((void**)&p_xw, g_xw);
    cudaGetSymbolAddress((void**)&p_deg, g_deg);
    cudaGetSymbolAddress((void**)&p_dinv, g_dinv);
    cudaGetSymbolAddress((void**)&p_cnt, g_cnt);
    cudaGetSymbolAddress((void**)&p_rowptr, g_rowptr);
    cudaGetSymbolAddress((void**)&p_cursor, g_cursor);
    cudaGetSymbolAddress((void**)&p_bsum, g_bsum);
    cudaGetSymbolAddress((void**)&p_eidx, g_eidx);
    cudaGetSymbolAddress((void**)&p_enorm, g_enorm);

    __nv_bfloat16 *p_xhi, *p_xlo, *p_ahi, *p_alo;
    __nv_bfloat16 *hA_hi, *hA_lo, *hB_hi, *hB_lo;
    cudaGetSymbolAddress((void**)&p_xhi, g_xhi);
    cudaGetSymbolAddress((void**)&p_xlo, g_xlo);
    cudaGetSymbolAddress((void**)&p_ahi, g_ahi);
    cudaGetSymbolAddress((void**)&p_alo, g_alo);
    cudaGetSymbolAddress((void**)&hA_hi, g_hAhi);
    cudaGetSymbolAddress((void**)&hA_lo, g_hAlo);
    cudaGetSymbolAddress((void**)&hB_hi, g_hBhi);
    cudaGetSymbolAddress((void**)&hB_lo, g_hBlo);

    __nv_bfloat16 *w_lin_h, *w_lin_l, *w_conv_h, *w_conv_l, *w_ih_h, *w_ih_l,
                  *w_hh_h, *w_hh_l, *w_fc_h, *w_fc_l;
    cudaGetSymbolAddress((void**)&w_lin_h, g_wlin_hi);
    cudaGetSymbolAddress((void**)&w_lin_l, g_wlin_lo);
    cudaGetSymbolAddress((void**)&w_conv_h, g_wconv_hi);
    cudaGetSymbolAddress((void**)&w_conv_l, g_wconv_lo);
    cudaGetSymbolAddress((void**)&w_ih_h, g_wih_hi);
    cudaGetSymbolAddress((void**)&w_ih_l, g_wih_lo);
    cudaGetSymbolAddress((void**)&w_hh_h, g_whh_hi);
    cudaGetSymbolAddress((void**)&w_hh_l, g_whh_lo);
    cudaGetSymbolAddress((void**)&w_fc_h, g_wfc_hi);
    cudaGetSymbolAddress((void**)&w_fc_l, g_wfc_lo);

    const int T = 256;
    auto cdiv = [](int a, int b) { return (a + b - 1) / b; };

    static bool attr_done = false;
    if (!attr_done) {
        cudaFuncSetAttribute(gemm_bf16<1,2>, cudaFuncAttributeMaxDynamicSharedMemorySize, GEMM_SMEM);
        cudaFuncSetAttribute(gemm_bf16<0,0>, cudaFuncAttributeMaxDynamicSharedMemorySize, GEMM_SMEM);
        cudaFuncSetAttribute(gru_mega, cudaFuncAttributeMaxDynamicSharedMemorySize, MEGA_SMEM);
        attr_done = true;
    }

    // ---- weight prep ----
    wsplit_kernel<<<cdiv(128 * 128, T), T>>>(linW, w_lin_h, w_lin_l, 128, 128, 1);
    for (int l = 0; l < 3; l++)
        wsplit_kernel<<<cdiv(128 * 128, T), T>>>(convW + (size_t)l * 16384,
            w_conv_h + (size_t)l * 16384, w_conv_l + (size_t)l * 16384, 128, 128, 1);
    wsplit_kernel<<<cdiv(G3 * 128, T), T>>>(Wih, w_ih_h, w_ih_l, G3, G3, 0);
    wsplit_kernel<<<cdiv(G3 * 128, T), T>>>(Whh, w_hh_h, w_hh_l, G3, G3, 0);
    wsplit_kernel<<<cdiv(64 * 128, T), T>>>(fcW, w_fc_h, w_fc_l, C, 64, 1);

    // ---- activation prep ----
    asplit_kernel<<<cdiv(N * HDIM, T), T>>>(x, p_xhi, p_xlo, N * HDIM);
    asplit_kernel<<<cdiv(N * HDIM, T), T>>>(h0, hA_hi, hA_lo, N * HDIM);

    // ---- graph prep: deg/dinv + CSR build ----
    init_deg_kernel<<<cdiv(N, T), T>>>(p_deg, p_cnt, N);
    deg_accum_kernel<<<cdiv(E, T), T>>>(dst, ew, p_deg, p_cnt, E);
    dinv_kernel<<<cdiv(N, T), T>>>(p_deg, p_dinv, N);
    const int NB = cdiv(N, 1024);
    scan_block<<<NB, 1024>>>(p_cnt, p_rowptr, p_bsum, N);
    scan_tops<<<1, 32>>>(p_bsum, NB);
    scan_add<<<NB, 1024>>>(p_rowptr, p_cursor, p_bsum, N, E);
    fill_kernel<<<cdiv(E, T), T>>>(src, dst, ew, p_dinv, p_cursor, p_eidx, p_enorm, E);

    const int gy = cdiv(N, 128);   // 782
    const int gy64 = cdiv(N, 64);  // 1563

    // xh = relu(x @ linW + linB) -> bf16 split
    gemm_bf16<1,2><<<dim3(2, gy), 256, GEMM_SMEM>>>(p_xhi, p_xlo, w_lin_h, w_lin_l,
        linB, nullptr, p_ahi, p_alo, N, 128);

    // GRU 1: hA -> hB
    gru_mega<<<dim3(2, gy64), 256, MEGA_SMEM>>>(p_ahi, p_alo, hA_hi, hA_lo,
        w_ih_h, w_ih_l, w_hh_h, w_hh_l, bih, bhh, hB_hi, hB_lo, N);

    __nv_bfloat16 *cur_hi = hB_hi, *cur_lo = hB_lo;
    __nv_bfloat16 *nxt_hi = hA_hi, *nxt_lo = hA_lo;

    // 3 GCN layers + GRU
    for (int l = 0; l < 3; l++) {
        gemm_bf16<0,0><<<dim3(2, gy), 256, GEMM_SMEM>>>(p_ahi, p_alo,
            w_conv_h + (size_t)l * 16384, w_conv_l + (size_t)l * 16384,
            nullptr, p_xw, nullptr, nullptr, N, 128);
        aggregate_kernel<<<cdiv(N * 32, T), T>>>(p_rowptr, p_eidx, p_enorm, p_xw,
            p_dinv, convB + (size_t)l * HDIM, p_ahi, p_alo, N);
        gru_mega<<<dim3(2, gy64), 256, MEGA_SMEM>>>(p_ahi, p_alo, cur_hi, cur_lo,
            w_ih_h, w_ih_l, w_hh_h, w_hh_l, bih, bhh, nxt_hi, nxt_lo, N);
        __nv_bfloat16* t;
        t = cur_hi; cur_hi = nxt_hi; nxt_hi = t;
        t = cur_lo; cur_lo = nxt_lo; nxt_lo = t;
    }

    // out = h @ fcW + fcB
    gemm_bf16<0,0><<<dim3(1, gy), 256, GEMM_SMEM>>>(cur_hi, cur_lo, w_fc_h, w_fc_l,
        fcB, out, nullptr, nullptr, N, C);
}